// round 12
// baseline (speedup 1.0000x reference)
#include <cuda_runtime.h>
#include <cuda_fp16.h>
#include <cstdint>

#define DINLINE __device__ __forceinline__

// ======================= scratch (device globals) =======================
__device__ __align__(16) __half g_O1[(size_t)64*65*65*200]; // L1 out fp16 NHWC
__device__ __align__(16) __half g_O2[(size_t)64*31*31*400]; // L2 out fp16 NHWC
__device__ __align__(16) __half g_O3[(size_t)64*15*15*800]; // L3 out fp16 NHWC
__device__ __align__(16) float  g_P4[(size_t)3*10880*64];   // L4 split-K partials

// L1 im2col: A1[Npad=270592][64]
__device__ __align__(16) __half g_A1[(size_t)270592*64];
// weights fp16 [OCpad][Kpad]
__device__ __align__(16) __half g_B1[(size_t)256*64];
__device__ __align__(16) __half g_B2[(size_t)512*1856];
__device__ __align__(16) __half g_B3[(size_t)896*3648];
__device__ __align__(16) __half g_B4[(size_t)64*7232];

// ======================= helpers =======================
DINLINE uint32_t smem_u32(const void* p){
    uint32_t a;
    asm("{ .reg .u64 t; cvta.to.shared.u64 t, %1; cvt.u32.u64 %0, t; }" : "=r"(a) : "l"(p));
    return a;
}
DINLINE void cp16(uint32_t dst, const void* src){
    asm volatile("cp.async.cg.shared.global [%0], [%1], 16;" :: "r"(dst), "l"(src));
}
DINLINE void cp16z(uint32_t dst, const void* src, uint32_t srcsize){
    asm volatile("cp.async.cg.shared.global [%0], [%1], 16, %2;" :: "r"(dst), "l"(src), "r"(srcsize));
}
DINLINE void cp_commit(){ asm volatile("cp.async.commit_group;" ::: "memory"); }
DINLINE void cp_wait1(){ asm volatile("cp.async.wait_group 1;" ::: "memory"); }

DINLINE void ldmx4(uint32_t r[4], uint32_t addr){
    asm volatile("ldmatrix.sync.aligned.m8n8.x4.shared.b16 {%0,%1,%2,%3}, [%4];"
        : "=r"(r[0]), "=r"(r[1]), "=r"(r[2]), "=r"(r[3]) : "r"(addr));
}
DINLINE void mma_fp16(float c[4], const uint32_t a[4], uint32_t b0, uint32_t b1){
    asm volatile("mma.sync.aligned.m16n8k16.row.col.f32.f16.f16.f32 "
        "{%0,%1,%2,%3}, {%4,%5,%6,%7}, {%8,%9}, {%0,%1,%2,%3};"
        : "+f"(c[0]), "+f"(c[1]), "+f"(c[2]), "+f"(c[3])
        : "r"(a[0]), "r"(a[1]), "r"(a[2]), "r"(a[3]), "r"(b0), "r"(b1));
}

// ======================= transforms =======================
__global__ void k_wcvt(const float* __restrict__ W, __half* __restrict__ Bw,
                       int OC, int IC, int Klayer, int Kpad, int OCpad)
{
    long idx = (long)blockIdx.x*blockDim.x + threadIdx.x;
    if (idx >= (long)OCpad * Kpad) return;
    int oc = (int)(idx / Kpad);
    int kk = (int)(idx - (long)oc*Kpad);
    __half out = __float2half_rn(0.f);
    if (oc < OC && kk < Klayer){
        int tap = kk/IC, c = kk - tap*IC;
        out = __float2half_rn(W[((size_t)oc*IC + c)*9 + tap]);
    }
    Bw[idx] = out;
}

// layer 1 gather directly from x NCHW: fp16, Kpad=64, cols [0:27) valid
__global__ void k_gather1(const float* __restrict__ X, __half* __restrict__ A,
                          const int* __restrict__ selh, const int* __restrict__ selw)
{
    int n = blockIdx.x*blockDim.x + threadIdx.x;
    if (n >= 270592) return;
    __half row[64];
#pragma unroll
    for (int i=0;i<64;i++) row[i] = __float2half_rn(0.f);
    if (n < 270400){
        int b = n / 4225, p = n - b*4225;
        int oy = p/65, ox = p - oy*65;
        int ph = oy*2 + selh[p], pw = ox*2 + selw[p];
        const float* xb = X + (size_t)b*3*132*132 + ph*132 + pw;
#pragma unroll
        for (int ic=0; ic<3; ic++){
#pragma unroll
            for (int ky=0; ky<3; ky++){
#pragma unroll
                for (int kx=0; kx<3; kx++){
                    float v = xb[(size_t)ic*132*132 + ky*132 + kx];
                    row[(ky*3 + kx)*3 + ic] = __float2half_rn(v);
                }
            }
        }
    }
    uint4* dst = (uint4*)(A + (size_t)n*64);
    uint4* s = (uint4*)row;
#pragma unroll
    for (int i=0;i<8;i++) dst[i] = s[i];
}

// L4 combine
__global__ void k_out4(const float* __restrict__ P4, const float* __restrict__ bias,
                       float* __restrict__ out)
{
    int idx = blockIdx.x*blockDim.x + threadIdx.x;
    if (idx >= 108160) return;
    int n = idx / 10, oc = idx - n*10;
    const size_t ps = (size_t)10880*64;
    float v = P4[(size_t)n*64 + oc] + P4[ps + (size_t)n*64 + oc]
            + P4[2*ps + (size_t)n*64 + oc] + __ldg(&bias[oc]);
    int b = n / 169, p = n - b*169;
    out[(b*10 + oc)*169 + p] = v;
}

// ======================= persistent L1 GEMM (unchanged, proven) =======================
static constexpr int SMEM_L1 = 16384 * 4;

__global__ __launch_bounds__(256, 2)
void k_hmma1(const __half* __restrict__ A, const __half* __restrict__ Bw,
             const float* __restrict__ bias, const int* __restrict__ mask,
             __half* __restrict__ Out)
{
    extern __shared__ char smem[];
    const uint32_t sb = smem_u32(smem);
    const int tid = threadIdx.x, lane = tid & 31, warp = tid >> 5;
    const int wm = warp >> 1, wn = warp & 1;

    const int l_row = tid >> 3, l_ch = tid & 7;
    const uint32_t l_soff = (uint32_t)(l_row*128 + ((l_ch ^ (l_row&7))<<4));

    {
        const __half* Bg = Bw + (size_t)(blockIdx.x*128 + l_row)*64 + l_ch*8;
#pragma unroll
        for (int i=0;i<4;i++) cp16(sb + l_soff + i*4096, Bg + i*32*64);
    }

    const int NBLK = 2114, STEP = gridDim.y;
    auto loadA = [&](int it){
        int nb = blockIdx.y + it*STEP;
        if (nb >= NBLK) return;
        const __half* Ag = A + ((size_t)nb*128 + l_row)*64 + l_ch*8;
        uint32_t sA = sb + 16384 + (it%3)*16384;
#pragma unroll
        for (int j=0;j<4;j++) cp16(sA + l_soff + j*4096, Ag + j*32*64);
    };

    loadA(0); cp_commit();
    loadA(1); cp_commit();

    const uint32_t rowA = (uint32_t)((wm*32 + (lane & 15)) * 128);
    const uint32_t rowB = (uint32_t)((wn*64 + (lane & 15)) * 128);
    const uint32_t chbase = (uint32_t)(lane >> 4);
    const uint32_t chxor  = (uint32_t)(lane & 7);
    uint32_t aB[4];
#pragma unroll
    for (int i=0;i<4;i++) aB[i] = sb + rowB + i*16*128;

    const int niter = (NBLK - blockIdx.y + STEP - 1) / STEP;
#pragma unroll 1
    for (int it = 0; it < niter; it++){
        cp_wait1();
        __syncthreads();
        loadA(it+2); cp_commit();

        const uint32_t sA = sb + 16384 + (it%3)*16384;
        const uint32_t aA0 = sA + rowA, aA1 = aA0 + 16*128;

        float c[2][8][4];
#pragma unroll
        for (int i=0;i<2;i++)
#pragma unroll
            for (int j=0;j<8;j++)
#pragma unroll
                for (int k=0;k<4;k++) c[i][j][k] = 0.f;

        uint32_t a[2][2][4], b[2][4][4];
        {
            const uint32_t ch = (chbase ^ chxor) << 4;
            ldmx4(a[0][0], aA0 + ch); ldmx4(a[0][1], aA1 + ch);
#pragma unroll
            for (int i=0;i<4;i++) ldmx4(b[0][i], aB[i] + ch);
        }
#pragma unroll
        for (int ks = 0; ks < 4; ks++){
            const int cur = ks & 1, nxt = cur ^ 1;
            if (ks < 3){
                const uint32_t ch = (((ks+1)*2 + chbase) ^ chxor) << 4;
                ldmx4(a[nxt][0], aA0 + ch); ldmx4(a[nxt][1], aA1 + ch);
#pragma unroll
                for (int i=0;i<4;i++) ldmx4(b[nxt][i], aB[i] + ch);
            }
#pragma unroll
            for (int mi = 0; mi < 2; mi++)
#pragma unroll
                for (int nj = 0; nj < 8; nj++)
                    mma_fp16(c[mi][nj], a[cur][mi],
                             b[cur][nj>>1][nj&1], b[cur][nj>>1][2+(nj&1)]);
        }

        const int nb = blockIdx.y + it*STEP;
        const int gm0 = nb*128 + wm*32;
        const int oc0 = blockIdx.x*128 + wn*64;
#pragma unroll
        for (int mi = 0; mi < 2; mi++){
#pragma unroll
            for (int half = 0; half < 2; half++){
                int n = gm0 + mi*16 + half*8 + (lane >> 2);
                if (n >= 270400) continue;
                int p = n % 4225;
                int mk = mask[p];
#pragma unroll
                for (int nj = 0; nj < 8; nj++){
                    int oc = oc0 + nj*8 + (lane & 3)*2;
                    if (oc < 200){
                        float v0 = (mk ? c[mi][nj][half*2+0] : 0.f) + __ldg(&bias[oc]);
                        float v1 = (mk ? c[mi][nj][half*2+1] : 0.f) + __ldg(&bias[oc+1]);
                        v0 = fmaxf(v0, 0.f); v1 = fmaxf(v1, 0.f);
                        __half2* orow = (__half2*)(Out + (size_t)n * 200 + oc);
                        *orow = __floats2half2_rn(v0, v1);
                    }
                }
            }
        }
    }
}

// ======================= L2/L3: 4-warp fused GEMM, 64x64 warp tiles =======================
// CTA 128(n) x 128(oc), 128 threads, warps 2x2, warp tile 64x64. 2 CTAs/SM.
// 3-stage ring of 32KB; fused im2col A-load with smem offset table.
static constexpr int STAGE = 32768;
static constexpr int SMEM_HM = 3 * STAGE + 512 + 3712;

__global__ __launch_bounds__(128, 2)
void k_hmma4(const __half* __restrict__ B,
             const float* __restrict__ bias, const int* __restrict__ mask,
             __half* __restrict__ Out,
             int Kpad, int NC, int OC, int P, int Nreal,
             const __half* __restrict__ Src, const int* __restrict__ selh,
             const int* __restrict__ selw, int IW, int ICp, int OW,
             int Klayer)
{
    extern __shared__ char smem[];
    const uint32_t sb = smem_u32(smem);
    int* s_base = (int*)(smem + 3*STAGE);
    int* s_off  = (int*)(smem + 3*STAGE + 512);
    const int tid = threadIdx.x, lane = tid & 31, warp = tid >> 5;
    const int wm = warp >> 1, wn = warp & 1;     // 2x2; warp tile 64x64

    const long ld = (long)Kpad;
    const int l_row = tid >> 3, l_ch = tid & 7;  // l_row 0..15
    const uint32_t l_soff = (uint32_t)(l_row*128 + ((l_ch ^ (l_row&7))<<4));
    const __half* Bg = B + (size_t)(blockIdx.x*128 + l_row) * ld + l_ch*8;
    const long ld16 = 16*ld;

    {
        int n = blockIdx.y*128 + tid;
        if (n >= Nreal) n = Nreal - 1;
        int b = n / P, p = n - b*P;
        int oy = p / OW, ox = p - oy*OW;
        int ph = oy*2 + selh[p], pw = ox*2 + selw[p];
        s_base[tid] = (b*IW + ph)*IW + pw;       // square: IH==IW
    }
    for (int j = tid; j < (Klayer >> 3); j += 128){
        int k = j << 3;
        int tap = k / ICp, c = k - tap*ICp;
        int ky = tap/3, kx = tap - 3*ky;
        s_off[j] = (ky*IW + kx)*ICp + c;
    }
    __syncthreads();

    auto loadA = [&](int chunk, uint32_t sA){
        int j = chunk*8 + l_ch;
        uint32_t sz = ((j << 3) < Klayer) ? 16u : 0u;
        long off = sz ? (long)s_off[j] : 0;
#pragma unroll
        for (int i=0;i<8;i++){
            int row = l_row + i*16;
            const __half* src = Src + (size_t)s_base[row]*ICp + off;
            cp16z(sA + l_soff + i*2048, src, sz);
        }
    };
    auto loadB = [&](int chunk, uint32_t sB){
#pragma unroll
        for (int i=0;i<8;i++) cp16(sB + l_soff + i*2048, Bg + chunk*64 + i*ld16);
    };

    const uint32_t rowA = (uint32_t)((wm*64 + (lane & 15)) * 128);
    const uint32_t rowB = (uint32_t)((wn*64 + (lane & 15)) * 128);
    const uint32_t chbase = (uint32_t)(lane >> 4);
    const uint32_t chxor  = (uint32_t)(lane & 7);

    float c[4][8][4];
#pragma unroll
    for (int i=0;i<4;i++)
#pragma unroll
        for (int j=0;j<8;j++)
#pragma unroll
            for (int k=0;k<4;k++) c[i][j][k] = 0.f;

    loadA(0, sb);       loadB(0, sb + 16384);       cp_commit();
    if (NC > 1){ loadA(1, sb + STAGE); loadB(1, sb + STAGE + 16384); }
    cp_commit();

#pragma unroll 1
    for (int cc = 0; cc < NC; cc++){
        cp_wait1();
        __syncthreads();
        if (cc + 2 < NC){
            uint32_t sA = sb + ((cc+2) % 3)*STAGE;
            loadA(cc+2, sA); loadB(cc+2, sA + 16384);
        }
        cp_commit();

        const uint32_t sA = sb + (cc % 3)*STAGE;
        const uint32_t sB = sA + 16384;
#pragma unroll
        for (int ks = 0; ks < 4; ks++){
            const uint32_t ch = ((ks*2 + chbase) ^ chxor) << 4;
            uint32_t a[4][4], b[4][4];
#pragma unroll
            for (int mi = 0; mi < 4; mi++)
                ldmx4(a[mi], sA + rowA + mi*16*128 + ch);
#pragma unroll
            for (int ni = 0; ni < 4; ni++)
                ldmx4(b[ni], sB + rowB + ni*16*128 + ch);
#pragma unroll
            for (int mi = 0; mi < 4; mi++)
#pragma unroll
                for (int nj = 0; nj < 8; nj++)
                    mma_fp16(c[mi][nj], a[mi],
                             b[nj>>1][nj&1], b[nj>>1][2+(nj&1)]);
        }
    }

    const int gm0 = blockIdx.y*128 + wm*64;
    const int oc0 = blockIdx.x*128 + wn*64;
#pragma unroll
    for (int mi = 0; mi < 4; mi++){
#pragma unroll
        for (int half = 0; half < 2; half++){
            int n = gm0 + mi*16 + half*8 + (lane >> 2);
            if (n >= Nreal) continue;
            int p = n % P;
            int mk = mask[p];
            __half* orow = Out + (size_t)n * OC;
#pragma unroll
            for (int nj = 0; nj < 8; nj++){
                int oc = oc0 + nj*8 + (lane & 3)*2;
                if (oc < OC){
                    float v0 = (mk ? c[mi][nj][half*2+0] : 0.f) + __ldg(&bias[oc]);
                    float v1 = (mk ? c[mi][nj][half*2+1] : 0.f) + __ldg(&bias[oc+1]);
                    v0 = fmaxf(v0, 0.f); v1 = fmaxf(v1, 0.f);
                    *(__half2*)(orow + oc) = __floats2half2_rn(v0, v1);
                }
            }
        }
    }
}

// ======================= L4: 8-warp fused GEMM, split-K (unchanged) =======================
static constexpr int SPLITC = 38;

__global__ __launch_bounds__(256, 2)
void k_hmma_l4(const __half* __restrict__ B,
               void* __restrict__ Outv,
               int Kpad, int NC, int P, int Nreal,
               const __half* __restrict__ Src, int IW, int ICp, int OW,
               int Klayer)
{
    extern __shared__ char smem[];
    const uint32_t sb = smem_u32(smem);
    int* s_base = (int*)(smem + 3*STAGE);
    int* s_off  = (int*)(smem + 3*STAGE + 512);
    const int tid = threadIdx.x, lane = tid & 31, warp = tid >> 5;
    const int wm = warp >> 1, wn = warp & 1;
    constexpr int NT = 64;

    const long ld = (long)Kpad;
    const int l_row = tid >> 3, l_ch = tid & 7;
    const uint32_t l_soff = (uint32_t)(l_row*128 + ((l_ch ^ (l_row&7))<<4));
    const __half* Bg = B + (size_t)l_row * ld + l_ch*8;
    const long ld32 = 32*ld;

    const int cbase = (int)blockIdx.z * SPLITC;
    const int NCl   = min(SPLITC, NC - cbase);

    if (tid < 128){
        int n = blockIdx.y*128 + tid;
        if (n >= Nreal) n = Nreal - 1;
        int b = n / P, p = n - b*P;
        int oy = p / OW, ox = p - oy*OW;
        s_base[tid] = (b*IW + oy)*IW + ox;
    }
    for (int j = tid; j < (Klayer >> 3); j += 256){
        int k = j << 3;
        int tap = k / ICp, c = k - tap*ICp;
        int ky = tap/3, kx = tap - 3*ky;
        s_off[j] = (ky*IW + kx)*ICp + c;
    }
    __syncthreads();

    auto loadA = [&](int chunk, uint32_t sA){
        int j = chunk*8 + l_ch;
        uint32_t sz = ((j << 3) < Klayer) ? 16u : 0u;
        long off = sz ? (long)s_off[j] : 0;
#pragma unroll
        for (int i=0;i<4;i++){
            int row = l_row + i*32;
            const __half* src = Src + (size_t)s_base[row]*ICp + off;
            cp16z(sA + l_soff + i*4096, src, sz);
        }
    };
    auto loadB = [&](int chunk, uint32_t sB){
#pragma unroll
        for (int i=0;i<NT/32;i++) cp16(sB + l_soff + i*4096, Bg + chunk*64 + i*ld32);
    };

    const uint32_t rowA = (uint32_t)((wm*32 + (lane & 15)) * 128);
    const uint32_t rowB = (uint32_t)((wn*(NT/2) + (lane & 15)) * 128);
    const uint32_t chbase = (uint32_t)(lane >> 4);
    const uint32_t chxor  = (uint32_t)(lane & 7);

    constexpr int NJ = NT/16;
    constexpr int NB = NT/32;
    float c[2][NJ][4];
#pragma unroll
    for (int i=0;i<2;i++)
#pragma unroll
        for (int j=0;j<NJ;j++)
#pragma unroll
            for (int k=0;k<4;k++) c[i][j][k] = 0.f;

    loadA(cbase, sb);       loadB(cbase, sb + 16384);       cp_commit();
    if (NCl > 1){ loadA(cbase+1, sb + STAGE); loadB(cbase+1, sb + STAGE + 16384); }
    cp_commit();

#pragma unroll 1
    for (int cc = 0; cc < NCl; cc++){
        cp_wait1();
        __syncthreads();
        if (cc + 2 < NCl){
            uint32_t sA = sb + ((cc+2) % 3)*STAGE;
            loadA(cbase+cc+2, sA); loadB(cbase+cc+2, sA + 16384);
        }
        cp_commit();

        const uint32_t sA = sb + (cc % 3)*STAGE;
        const uint32_t sB = sA + 16384;
        const uint32_t aA0 = sA + rowA, aA1 = aA0 + 16*128;
        uint32_t aB[NB];
#pragma unroll
        for (int i=0;i<NB;i++) aB[i] = sB + rowB + i*16*128;

        uint32_t a[2][2][4], b[2][NB][4];
        {
            const uint32_t ch = (chbase ^ chxor) << 4;
            ldmx4(a[0][0], aA0 + ch); ldmx4(a[0][1], aA1 + ch);
#pragma unroll
            for (int i=0;i<NB;i++) ldmx4(b[0][i], aB[i] + ch);
        }
#pragma unroll
        for (int ks = 0; ks < 4; ks++){
            const int cur = ks & 1, nxt = cur ^ 1;
            if (ks < 3){
                const uint32_t ch = (((ks+1)*2 + chbase) ^ chxor) << 4;
                ldmx4(a[nxt][0], aA0 + ch); ldmx4(a[nxt][1], aA1 + ch);
#pragma unroll
                for (int i=0;i<NB;i++) ldmx4(b[nxt][i], aB[i] + ch);
            }
#pragma unroll
            for (int mi = 0; mi < 2; mi++)
#pragma unroll
                for (int nj = 0; nj < NJ; nj++)
                    mma_fp16(c[mi][nj], a[cur][mi],
                             b[cur][nj>>1][nj&1], b[cur][nj>>1][2+(nj&1)]);
        }
    }

    const int gm0 = blockIdx.y*128 + wm*32;
    const int oc0 = wn*(NT/2);
#pragma unroll
    for (int mi = 0; mi < 2; mi++){
#pragma unroll
        for (int half = 0; half < 2; half++){
            int n = gm0 + mi*16 + half*8 + (lane >> 2);
            if (n >= Nreal) continue;
#pragma unroll
            for (int nj = 0; nj < NJ; nj++){
                int oc = oc0 + nj*8 + (lane & 3)*2;
                float* o = (float*)Outv + (size_t)blockIdx.z*10880*64
                         + (size_t)n*64 + oc;
                float2 v = {c[mi][nj][half*2+0], c[mi][nj][half*2+1]};
                *(float2*)o = v;
            }
        }
    }
}

// ======================= launch =======================
extern "C" void kernel_launch(void* const* d_in, const int* in_sizes, int n_in,
                              void* d_out, int out_size) {
    const float* x     = (const float*)d_in[0];
    const float* w1    = (const float*)d_in[1];
    const float* b1    = (const float*)d_in[2];
    const float* w2    = (const float*)d_in[3];
    const float* b2    = (const float*)d_in[4];
    const float* w3    = (const float*)d_in[5];
    const float* b3    = (const float*)d_in[6];
    const float* w4    = (const float*)d_in[7];
    const float* b4    = (const float*)d_in[8];
    const int*   selh1 = (const int*)d_in[9];
    const int*   selw1 = (const int*)d_in[10];
    const int*   mask1 = (const int*)d_in[11];
    const int*   selh2 = (const int*)d_in[12];
    const int*   selw2 = (const int*)d_in[13];
    const int*   mask2 = (const int*)d_in[14];
    const int*   selh3 = (const int*)d_in[15];
    const int*   selw3 = (const int*)d_in[16];
    const int*   mask3 = (const int*)d_in[17];

    float *pP4;
    __half *pO1, *pO2, *pO3, *pA1, *pB1, *pB2, *pB3, *pB4;
    cudaGetSymbolAddress((void**)&pO1, g_O1);
    cudaGetSymbolAddress((void**)&pO2, g_O2);
    cudaGetSymbolAddress((void**)&pO3, g_O3);
    cudaGetSymbolAddress((void**)&pP4, g_P4);
    cudaGetSymbolAddress((void**)&pA1, g_A1);
    cudaGetSymbolAddress((void**)&pB1, g_B1);
    cudaGetSymbolAddress((void**)&pB2, g_B2);
    cudaGetSymbolAddress((void**)&pB3, g_B3);
    cudaGetSymbolAddress((void**)&pB4, g_B4);

    cudaFuncSetAttribute((const void*)k_hmma1,
                         cudaFuncAttributeMaxDynamicSharedMemorySize, SMEM_L1);
    cudaFuncSetAttribute((const void*)k_hmma4,
                         cudaFuncAttributeMaxDynamicSharedMemorySize, SMEM_HM);
    cudaFuncSetAttribute((const void*)k_hmma_l4,
                         cudaFuncAttributeMaxDynamicSharedMemorySize, SMEM_HM);

    // ---- layer 1: gather from x NCHW + persistent-B GEMM ----
    k_gather1<<<(270592 + 255) / 256, 256>>>(x, pA1, selh1, selw1);
    k_wcvt<<<(256*64 + 255) / 256, 256>>>(w1, pB1, 200, 3, 27, 64, 256);
    k_hmma1<<<dim3(2, 148), 256, SMEM_L1>>>(pA1, pB1, b1, mask1, pO1);

    // ---- layer 2: 4-warp fused GEMM, K=1800, Kpad=1856, NC=29 ----
    {
        long wt = (long)512 * 1856;
        k_wcvt<<<(unsigned)((wt + 255) / 256), 256>>>(w2, pB2, 400, 200, 1800, 1856, 512);
        k_hmma4<<<dim3(4, 482), 128, SMEM_HM>>>(
            pB2, b2, mask2, pO2, 1856, 29, 400, 961, 61504,
            pO1, selh2, selw2, 65, 200, 31, 1800);
    }

    // ---- layer 3: 4-warp fused GEMM, K=3600, Kpad=3648, NC=57 ----
    {
        long wt = (long)896 * 3648;
        k_wcvt<<<(unsigned)((wt + 255) / 256), 256>>>(w3, pB3, 800, 400, 3600, 3648, 896);
        k_hmma4<<<dim3(7, 114), 128, SMEM_HM>>>(
            pB3, b3, mask3, pO3, 3648, 57, 800, 225, 14400,
            pO2, selh3, selw3, 31, 400, 15, 3600);
    }

    // ---- layer 4: fused dense GEMM, split-K x3 partials + combine ----
    {
        long wt = (long)64 * 7232;
        k_wcvt<<<(unsigned)((wt + 255) / 256), 256>>>(w4, pB4, 10, 800, 7200, 7232, 64);
        k_hmma_l4<<<dim3(1, 85, 3), 256, SMEM_HM>>>(
            pB4, pP4, 7232, 113, 169, 10816,
            pO3, 15, 800, 13, 7200);
        k_out4<<<(108160 + 255) / 256, 256>>>(pP4, b4, (float*)d_out);
    }
}

// round 13
// speedup vs baseline: 1.0516x; 1.0516x over previous
#include <cuda_runtime.h>
#include <cuda_fp16.h>
#include <cstdint>

#define DINLINE __device__ __forceinline__

// ======================= scratch (device globals) =======================
__device__ __align__(16) __half g_O1[(size_t)64*65*65*200]; // L1 out fp16 NHWC
__device__ __align__(16) __half g_O2[(size_t)64*31*31*400]; // L2 out fp16 NHWC
__device__ __align__(16) __half g_O3[(size_t)64*15*15*800]; // L3 out fp16 NHWC
__device__ __align__(16) float  g_P4[(size_t)3*10880*64];   // L4 split-K partials

// L1 im2col: A1[Npad=270592][64]
__device__ __align__(16) __half g_A1[(size_t)270592*64];
// weights fp16 [OCpad][Kpad]
__device__ __align__(16) __half g_B1[(size_t)256*64];
__device__ __align__(16) __half g_B2[(size_t)512*1856];
__device__ __align__(16) __half g_B3[(size_t)896*3648];
__device__ __align__(16) __half g_B4[(size_t)64*7232];

// ======================= helpers =======================
DINLINE uint32_t smem_u32(const void* p){
    uint32_t a;
    asm("{ .reg .u64 t; cvta.to.shared.u64 t, %1; cvt.u32.u64 %0, t; }" : "=r"(a) : "l"(p));
    return a;
}
DINLINE void cp16(uint32_t dst, const void* src){
    asm volatile("cp.async.cg.shared.global [%0], [%1], 16;" :: "r"(dst), "l"(src));
}
DINLINE void cp16z(uint32_t dst, const void* src, uint32_t srcsize){
    asm volatile("cp.async.cg.shared.global [%0], [%1], 16, %2;" :: "r"(dst), "l"(src), "r"(srcsize));
}
DINLINE void cp_commit(){ asm volatile("cp.async.commit_group;" ::: "memory"); }
DINLINE void cp_wait1(){ asm volatile("cp.async.wait_group 1;" ::: "memory"); }

DINLINE void ldmx4(uint32_t r[4], uint32_t addr){
    asm volatile("ldmatrix.sync.aligned.m8n8.x4.shared.b16 {%0,%1,%2,%3}, [%4];"
        : "=r"(r[0]), "=r"(r[1]), "=r"(r[2]), "=r"(r[3]) : "r"(addr));
}
DINLINE void mma_fp16(float c[4], const uint32_t a[4], uint32_t b0, uint32_t b1){
    asm volatile("mma.sync.aligned.m16n8k16.row.col.f32.f16.f16.f32 "
        "{%0,%1,%2,%3}, {%4,%5,%6,%7}, {%8,%9}, {%0,%1,%2,%3};"
        : "+f"(c[0]), "+f"(c[1]), "+f"(c[2]), "+f"(c[3])
        : "r"(a[0]), "r"(a[1]), "r"(a[2]), "r"(a[3]), "r"(b0), "r"(b1));
}

// ======================= transforms =======================
// One launch converts ALL four weight tensors.
DINLINE void wcvt_one(const float* W, __half* Bw, int OC, int IC, int Klayer,
                      int Kpad, long idx)
{
    int oc = (int)(idx / Kpad);
    int kk = (int)(idx - (long)oc*Kpad);
    __half out = __float2half_rn(0.f);
    if (oc < OC && kk < Klayer){
        int tap = kk/IC, c = kk - tap*IC;
        out = __float2half_rn(W[((size_t)oc*IC + c)*9 + tap]);
    }
    Bw[idx] = out;
}

static constexpr long WC1 = (long)256*64;
static constexpr long WC2 = WC1 + (long)512*1856;
static constexpr long WC3 = WC2 + (long)896*3648;
static constexpr long WC4 = WC3 + (long)64*7232;

__global__ void k_wcvt_all(const float* __restrict__ w1, const float* __restrict__ w2,
                           const float* __restrict__ w3, const float* __restrict__ w4,
                           __half* __restrict__ B1, __half* __restrict__ B2,
                           __half* __restrict__ B3, __half* __restrict__ B4)
{
    long idx = (long)blockIdx.x*blockDim.x + threadIdx.x;
    if (idx >= WC4) return;
    if (idx < WC1)      wcvt_one(w1, B1, 200, 3,   27,   64,   idx);
    else if (idx < WC2) wcvt_one(w2, B2, 400, 200, 1800, 1856, idx - WC1);
    else if (idx < WC3) wcvt_one(w3, B3, 800, 400, 3600, 3648, idx - WC2);
    else                wcvt_one(w4, B4, 10,  800, 7200, 7232, idx - WC3);
}

// layer 1 gather directly from x NCHW: fp16, Kpad=64, cols [0:27) valid
__global__ void k_gather1(const float* __restrict__ X, __half* __restrict__ A,
                          const int* __restrict__ selh, const int* __restrict__ selw)
{
    int n = blockIdx.x*blockDim.x + threadIdx.x;
    if (n >= 270592) return;
    __half row[64];
#pragma unroll
    for (int i=0;i<64;i++) row[i] = __float2half_rn(0.f);
    if (n < 270400){
        int b = n / 4225, p = n - b*4225;
        int oy = p/65, ox = p - oy*65;
        int ph = oy*2 + selh[p], pw = ox*2 + selw[p];
        const float* xb = X + (size_t)b*3*132*132 + ph*132 + pw;
#pragma unroll
        for (int ic=0; ic<3; ic++){
#pragma unroll
            for (int ky=0; ky<3; ky++){
#pragma unroll
                for (int kx=0; kx<3; kx++){
                    float v = xb[(size_t)ic*132*132 + ky*132 + kx];
                    row[(ky*3 + kx)*3 + ic] = __float2half_rn(v);
                }
            }
        }
    }
    uint4* dst = (uint4*)(A + (size_t)n*64);
    uint4* s = (uint4*)row;
#pragma unroll
    for (int i=0;i<8;i++) dst[i] = s[i];
}

// L4 combine
__global__ void k_out4(const float* __restrict__ P4, const float* __restrict__ bias,
                       float* __restrict__ out)
{
    int idx = blockIdx.x*blockDim.x + threadIdx.x;
    if (idx >= 108160) return;
    int n = idx / 10, oc = idx - n*10;
    const size_t ps = (size_t)10880*64;
    float v = P4[(size_t)n*64 + oc] + P4[ps + (size_t)n*64 + oc]
            + P4[2*ps + (size_t)n*64 + oc] + __ldg(&bias[oc]);
    int b = n / 169, p = n - b*169;
    out[(b*10 + oc)*169 + p] = v;
}

// ======================= persistent L1 GEMM =======================
static constexpr int SMEM_L1 = 16384 * 4;

__global__ __launch_bounds__(256, 2)
void k_hmma1(const __half* __restrict__ A, const __half* __restrict__ Bw,
             const float* __restrict__ bias, const int* __restrict__ mask,
             __half* __restrict__ Out)
{
    extern __shared__ char smem[];
    const uint32_t sb = smem_u32(smem);
    const int tid = threadIdx.x, lane = tid & 31, warp = tid >> 5;
    const int wm = warp >> 1, wn = warp & 1;

    const int l_row = tid >> 3, l_ch = tid & 7;
    const uint32_t l_soff = (uint32_t)(l_row*128 + ((l_ch ^ (l_row&7))<<4));

    {
        const __half* Bg = Bw + (size_t)(blockIdx.x*128 + l_row)*64 + l_ch*8;
#pragma unroll
        for (int i=0;i<4;i++) cp16(sb + l_soff + i*4096, Bg + i*32*64);
    }

    const int NBLK = 2114, STEP = gridDim.y;
    auto loadA = [&](int it){
        int nb = blockIdx.y + it*STEP;
        if (nb >= NBLK) return;
        const __half* Ag = A + ((size_t)nb*128 + l_row)*64 + l_ch*8;
        uint32_t sA = sb + 16384 + (it%3)*16384;
#pragma unroll
        for (int j=0;j<4;j++) cp16(sA + l_soff + j*4096, Ag + j*32*64);
    };

    loadA(0); cp_commit();
    loadA(1); cp_commit();

    const uint32_t rowA = (uint32_t)((wm*32 + (lane & 15)) * 128);
    const uint32_t rowB = (uint32_t)((wn*64 + (lane & 15)) * 128);
    const uint32_t chbase = (uint32_t)(lane >> 4);
    const uint32_t chxor  = (uint32_t)(lane & 7);
    uint32_t aB[4];
#pragma unroll
    for (int i=0;i<4;i++) aB[i] = sb + rowB + i*16*128;

    const int niter = (NBLK - blockIdx.y + STEP - 1) / STEP;
#pragma unroll 1
    for (int it = 0; it < niter; it++){
        cp_wait1();
        __syncthreads();
        loadA(it+2); cp_commit();

        const uint32_t sA = sb + 16384 + (it%3)*16384;
        const uint32_t aA0 = sA + rowA, aA1 = aA0 + 16*128;

        float c[2][8][4];
#pragma unroll
        for (int i=0;i<2;i++)
#pragma unroll
            for (int j=0;j<8;j++)
#pragma unroll
                for (int k=0;k<4;k++) c[i][j][k] = 0.f;

        uint32_t a[2][2][4], b[2][4][4];
        {
            const uint32_t ch = (chbase ^ chxor) << 4;
            ldmx4(a[0][0], aA0 + ch); ldmx4(a[0][1], aA1 + ch);
#pragma unroll
            for (int i=0;i<4;i++) ldmx4(b[0][i], aB[i] + ch);
        }
#pragma unroll
        for (int ks = 0; ks < 4; ks++){
            const int cur = ks & 1, nxt = cur ^ 1;
            if (ks < 3){
                const uint32_t ch = (((ks+1)*2 + chbase) ^ chxor) << 4;
                ldmx4(a[nxt][0], aA0 + ch); ldmx4(a[nxt][1], aA1 + ch);
#pragma unroll
                for (int i=0;i<4;i++) ldmx4(b[nxt][i], aB[i] + ch);
            }
#pragma unroll
            for (int mi = 0; mi < 2; mi++)
#pragma unroll
                for (int nj = 0; nj < 8; nj++)
                    mma_fp16(c[mi][nj], a[cur][mi],
                             b[cur][nj>>1][nj&1], b[cur][nj>>1][2+(nj&1)]);
        }

        const int nb = blockIdx.y + it*STEP;
        const int gm0 = nb*128 + wm*32;
        const int oc0 = blockIdx.x*128 + wn*64;
#pragma unroll
        for (int mi = 0; mi < 2; mi++){
#pragma unroll
            for (int half = 0; half < 2; half++){
                int n = gm0 + mi*16 + half*8 + (lane >> 2);
                if (n >= 270400) continue;
                int p = n % 4225;
                int mk = mask[p];
#pragma unroll
                for (int nj = 0; nj < 8; nj++){
                    int oc = oc0 + nj*8 + (lane & 3)*2;
                    if (oc < 200){
                        float v0 = (mk ? c[mi][nj][half*2+0] : 0.f) + __ldg(&bias[oc]);
                        float v1 = (mk ? c[mi][nj][half*2+1] : 0.f) + __ldg(&bias[oc+1]);
                        v0 = fmaxf(v0, 0.f); v1 = fmaxf(v1, 0.f);
                        __half2* orow = (__half2*)(Out + (size_t)n * 200 + oc);
                        *orow = __floats2half2_rn(v0, v1);
                    }
                }
            }
        }
    }
}

// ======================= HMMA GEMM (L2/L3/L4), 8 warps, 32x64 warp tiles =======================
static constexpr int STAGE = 32768;
static constexpr int SMEM_HM = 3 * STAGE + 512 + 3712;
static constexpr int SPLITC = 38;

template <int NT, int OUTM>   // OUTM: 1=fp16 NHWC, 3=fp32 split-K partials
__global__ __launch_bounds__(256, 2)
void k_hmma(const __half* __restrict__ B,
            const float* __restrict__ bias, const int* __restrict__ mask,
            void* __restrict__ Outv,
            int Kpad, int NC, int OC, int P, int Nreal, int relu,
            const __half* __restrict__ Src, const int* __restrict__ selh,
            const int* __restrict__ selw, int IW, int ICp, int OW,
            int stride, int Klayer)
{
    extern __shared__ char smem[];
    const uint32_t sb = smem_u32(smem);
    int* s_base = (int*)(smem + 3*STAGE);
    int* s_off  = (int*)(smem + 3*STAGE + 512);
    const int tid = threadIdx.x, lane = tid & 31, warp = tid >> 5;
    const int wm = warp >> 1, wn = warp & 1;

    const long ld = (long)Kpad;
    const int l_row = tid >> 3, l_ch = tid & 7;
    const uint32_t l_soff = (uint32_t)(l_row*128 + ((l_ch ^ (l_row&7))<<4));
    const __half* Bg = B + (size_t)(blockIdx.x*NT + l_row) * ld + l_ch*8;
    const long ld32 = 32*ld;

    const int cbase = (OUTM == 3) ? (int)blockIdx.z * SPLITC : 0;
    const int NCl   = (OUTM == 3) ? min(SPLITC, NC - cbase) : NC;

    if (tid < 128){
        int n = blockIdx.y*128 + tid;
        if (n >= Nreal) n = Nreal - 1;
        int b = n / P, p = n - b*P;
        int oy = p / OW, ox = p - oy*OW;
        int ph = oy*stride + (selh ? selh[p] : 0);
        int pw = ox*stride + (selw ? selw[p] : 0);
        s_base[tid] = (b*IW + ph)*IW + pw;
    }
    for (int j = tid; j < (Klayer >> 3); j += 256){
        int k = j << 3;
        int tap = k / ICp, c = k - tap*ICp;
        int ky = tap/3, kx = tap - 3*ky;
        s_off[j] = (ky*IW + kx)*ICp + c;
    }
    __syncthreads();

    auto loadA = [&](int chunk, uint32_t sA){
        int j = chunk*8 + l_ch;
        int k = j << 3;
        uint32_t sz = (k < Klayer) ? 16u : 0u;
        long off = sz ? (long)s_off[j] : 0;
#pragma unroll
        for (int i=0;i<4;i++){
            int row = l_row + i*32;
            const __half* src = Src + (size_t)s_base[row]*ICp + off;
            cp16z(sA + l_soff + i*4096, src, sz);
        }
    };
    auto loadB = [&](int chunk, uint32_t sB){
#pragma unroll
        for (int i=0;i<NT/32;i++) cp16(sB + l_soff + i*4096, Bg + chunk*64 + i*ld32);
    };

    const uint32_t rowA = (uint32_t)((wm*32 + (lane & 15)) * 128);
    const uint32_t rowB = (uint32_t)((wn*(NT/2) + (lane & 15)) * 128);
    const uint32_t chbase = (uint32_t)(lane >> 4);
    const uint32_t chxor  = (uint32_t)(lane & 7);

    constexpr int NJ = NT/16;
    constexpr int NB = NT/32;
    float c[2][NJ][4];
#pragma unroll
    for (int i=0;i<2;i++)
#pragma unroll
        for (int j=0;j<NJ;j++)
#pragma unroll
            for (int k=0;k<4;k++) c[i][j][k] = 0.f;

    loadA(cbase, sb);       loadB(cbase, sb + 16384);       cp_commit();
    if (NCl > 1){ loadA(cbase+1, sb + STAGE); loadB(cbase+1, sb + STAGE + 16384); }
    cp_commit();

#pragma unroll 1
    for (int cc = 0; cc < NCl; cc++){
        cp_wait1();
        __syncthreads();
        if (cc + 2 < NCl){
            uint32_t sA = sb + ((cc+2) % 3)*STAGE;
            loadA(cbase+cc+2, sA); loadB(cbase+cc+2, sA + 16384);
        }
        cp_commit();

        const uint32_t sA = sb + (cc % 3)*STAGE;
        const uint32_t sB = sA + 16384;
        const uint32_t aA0 = sA + rowA, aA1 = aA0 + 16*128;
        uint32_t aB[NB];
#pragma unroll
        for (int i=0;i<NB;i++) aB[i] = sB + rowB + i*16*128;

        uint32_t a[2][2][4], b[2][NB][4];
        {
            const uint32_t ch = (chbase ^ chxor) << 4;
            ldmx4(a[0][0], aA0 + ch); ldmx4(a[0][1], aA1 + ch);
#pragma unroll
            for (int i=0;i<NB;i++) ldmx4(b[0][i], aB[i] + ch);
        }
#pragma unroll
        for (int ks = 0; ks < 4; ks++){
            const int cur = ks & 1, nxt = cur ^ 1;
            if (ks < 3){
                const uint32_t ch = (((ks+1)*2 + chbase) ^ chxor) << 4;
                ldmx4(a[nxt][0], aA0 + ch); ldmx4(a[nxt][1], aA1 + ch);
#pragma unroll
                for (int i=0;i<NB;i++) ldmx4(b[nxt][i], aB[i] + ch);
            }
#pragma unroll
            for (int mi = 0; mi < 2; mi++)
#pragma unroll
                for (int nj = 0; nj < NJ; nj++)
                    mma_fp16(c[mi][nj], a[cur][mi],
                             b[cur][nj>>1][nj&1], b[cur][nj>>1][2+(nj&1)]);
        }
    }

    const int gm0 = blockIdx.y*128 + wm*32;
    const int oc0 = blockIdx.x*NT + wn*(NT/2);
#pragma unroll
    for (int mi = 0; mi < 2; mi++){
#pragma unroll
        for (int half = 0; half < 2; half++){
            int n = gm0 + mi*16 + half*8 + (lane >> 2);
            if (n >= Nreal) continue;
            int mk = 1;
            if (OUTM != 3 && mask){ int p = n % P; mk = mask[p]; }
#pragma unroll
            for (int nj = 0; nj < NJ; nj++){
                int oc = oc0 + nj*8 + (lane & 3)*2;
                if (oc < OC || OUTM == 3){
                    if (OUTM == 3){
                        float* o = (float*)Outv + (size_t)blockIdx.z*10880*64
                                 + (size_t)n*64 + oc;
                        float2 v = {c[mi][nj][half*2+0], c[mi][nj][half*2+1]};
                        *(float2*)o = v;
                    } else {
                        float v0 = (mk ? c[mi][nj][half*2+0] : 0.f) + __ldg(&bias[oc]);
                        float v1 = (mk ? c[mi][nj][half*2+1] : 0.f) + __ldg(&bias[oc+1]);
                        if (relu){ v0 = fmaxf(v0, 0.f); v1 = fmaxf(v1, 0.f); }
                        __half2* orow = (__half2*)((__half*)Outv + (size_t)n * OC + oc);
                        *orow = __floats2half2_rn(v0, v1);
                    }
                }
            }
        }
    }
}

// ======================= launch =======================
extern "C" void kernel_launch(void* const* d_in, const int* in_sizes, int n_in,
                              void* d_out, int out_size) {
    const float* x     = (const float*)d_in[0];
    const float* w1    = (const float*)d_in[1];
    const float* b1    = (const float*)d_in[2];
    const float* w2    = (const float*)d_in[3];
    const float* b2    = (const float*)d_in[4];
    const float* w3    = (const float*)d_in[5];
    const float* b3    = (const float*)d_in[6];
    const float* w4    = (const float*)d_in[7];
    const float* b4    = (const float*)d_in[8];
    const int*   selh1 = (const int*)d_in[9];
    const int*   selw1 = (const int*)d_in[10];
    const int*   mask1 = (const int*)d_in[11];
    const int*   selh2 = (const int*)d_in[12];
    const int*   selw2 = (const int*)d_in[13];
    const int*   mask2 = (const int*)d_in[14];
    const int*   selh3 = (const int*)d_in[15];
    const int*   selw3 = (const int*)d_in[16];
    const int*   mask3 = (const int*)d_in[17];

    float *pP4;
    __half *pO1, *pO2, *pO3, *pA1, *pB1, *pB2, *pB3, *pB4;
    cudaGetSymbolAddress((void**)&pO1, g_O1);
    cudaGetSymbolAddress((void**)&pO2, g_O2);
    cudaGetSymbolAddress((void**)&pO3, g_O3);
    cudaGetSymbolAddress((void**)&pP4, g_P4);
    cudaGetSymbolAddress((void**)&pA1, g_A1);
    cudaGetSymbolAddress((void**)&pB1, g_B1);
    cudaGetSymbolAddress((void**)&pB2, g_B2);
    cudaGetSymbolAddress((void**)&pB3, g_B3);
    cudaGetSymbolAddress((void**)&pB4, g_B4);

    cudaFuncSetAttribute((const void*)k_hmma1,
                         cudaFuncAttributeMaxDynamicSharedMemorySize, SMEM_L1);
    cudaFuncSetAttribute((const void*)k_hmma<128,1>,
                         cudaFuncAttributeMaxDynamicSharedMemorySize, SMEM_HM);
    cudaFuncSetAttribute((const void*)k_hmma<64,3>,
                         cudaFuncAttributeMaxDynamicSharedMemorySize, SMEM_HM);

    // ---- all weight conversions in ONE launch + L1 gather ----
    k_wcvt_all<<<(unsigned)((WC4 + 255) / 256), 256>>>(w1, w2, w3, w4,
                                                       pB1, pB2, pB3, pB4);
    k_gather1<<<(270592 + 255) / 256, 256>>>(x, pA1, selh1, selw1);

    // ---- layer 1: persistent-B GEMM ----
    k_hmma1<<<dim3(2, 148), 256, SMEM_L1>>>(pA1, pB1, b1, mask1, pO1);

    // ---- layer 2: fused gather GEMM, K=1800, Kpad=1856, NC=29, fp16 out ----
    k_hmma<128,1><<<dim3(4, 482), 256, SMEM_HM>>>(
        pB2, b2, mask2, pO2, 1856, 29, 400, 961, 61504, 1,
        pO1, selh2, selw2, 65, 200, 31, 2, 1800);

    // ---- layer 3: fused gather GEMM, K=3600, Kpad=3648, NC=57, fp16 out ----
    k_hmma<128,1><<<dim3(7, 114), 256, SMEM_HM>>>(
        pB3, b3, mask3, pO3, 3648, 57, 800, 225, 14400, 1,
        pO2, selh3, selw3, 31, 400, 15, 2, 3600);

    // ---- layer 4: fused dense GEMM, split-K x3 partials + combine ----
    k_hmma<64,3><<<dim3(1, 85, 3), 256, SMEM_HM>>>(
        pB4, b4, nullptr, pP4, 7232, 113, 10, 169, 10816, 0,
        pO3, nullptr, nullptr, 15, 800, 13, 1, 7200);
    k_out4<<<(108160 + 255) / 256, 256>>>(pP4, b4, (float*)d_out);
}

// round 14
// speedup vs baseline: 1.0697x; 1.0172x over previous
#include <cuda_runtime.h>
#include <cuda_fp16.h>
#include <cstdint>

#define DINLINE __device__ __forceinline__

// ======================= scratch (device globals) =======================
__device__ __align__(16) __half g_O1[(size_t)64*65*65*200]; // L1 out fp16 NHWC
__device__ __align__(16) __half g_O2[(size_t)64*31*31*400]; // L2 out fp16 NHWC
__device__ __align__(16) __half g_O3[(size_t)64*15*15*800]; // L3 out fp16 NHWC
__device__ __align__(16) float  g_P4[(size_t)3*10880*64];   // L4 split-K partials

// L1 im2col: A1[Npad=270592][32]  (K=27 -> Kpad=32)
__device__ __align__(16) __half g_A1[(size_t)270592*32];
// weights fp16 [OCpad][Kpad]
__device__ __align__(16) __half g_B1[(size_t)256*32];
__device__ __align__(16) __half g_B2[(size_t)512*1856];
__device__ __align__(16) __half g_B3[(size_t)896*3648];
__device__ __align__(16) __half g_B4[(size_t)64*7232];

// ======================= helpers =======================
DINLINE uint32_t smem_u32(const void* p){
    uint32_t a;
    asm("{ .reg .u64 t; cvta.to.shared.u64 t, %1; cvt.u32.u64 %0, t; }" : "=r"(a) : "l"(p));
    return a;
}
DINLINE void cp16(uint32_t dst, const void* src){
    asm volatile("cp.async.cg.shared.global [%0], [%1], 16;" :: "r"(dst), "l"(src));
}
DINLINE void cp16z(uint32_t dst, const void* src, uint32_t srcsize){
    asm volatile("cp.async.cg.shared.global [%0], [%1], 16, %2;" :: "r"(dst), "l"(src), "r"(srcsize));
}
DINLINE void cp_commit(){ asm volatile("cp.async.commit_group;" ::: "memory"); }
DINLINE void cp_wait1(){ asm volatile("cp.async.wait_group 1;" ::: "memory"); }

DINLINE void ldmx4(uint32_t r[4], uint32_t addr){
    asm volatile("ldmatrix.sync.aligned.m8n8.x4.shared.b16 {%0,%1,%2,%3}, [%4];"
        : "=r"(r[0]), "=r"(r[1]), "=r"(r[2]), "=r"(r[3]) : "r"(addr));
}
DINLINE void mma_fp16(float c[4], const uint32_t a[4], uint32_t b0, uint32_t b1){
    asm volatile("mma.sync.aligned.m16n8k16.row.col.f32.f16.f16.f32 "
        "{%0,%1,%2,%3}, {%4,%5,%6,%7}, {%8,%9}, {%0,%1,%2,%3};"
        : "+f"(c[0]), "+f"(c[1]), "+f"(c[2]), "+f"(c[3])
        : "r"(a[0]), "r"(a[1]), "r"(a[2]), "r"(a[3]), "r"(b0), "r"(b1));
}

// ======================= transforms =======================
DINLINE void wcvt_one(const float* W, __half* Bw, int OC, int IC, int Klayer,
                      int Kpad, long idx)
{
    int oc = (int)(idx / Kpad);
    int kk = (int)(idx - (long)oc*Kpad);
    __half out = __float2half_rn(0.f);
    if (oc < OC && kk < Klayer){
        int tap = kk/IC, c = kk - tap*IC;
        out = __float2half_rn(W[((size_t)oc*IC + c)*9 + tap]);
    }
    Bw[idx] = out;
}

static constexpr long WC1 = (long)256*32;
static constexpr long WC2 = WC1 + (long)512*1856;
static constexpr long WC3 = WC2 + (long)896*3648;
static constexpr long WC4 = WC3 + (long)64*7232;

__global__ void k_wcvt_all(const float* __restrict__ w1, const float* __restrict__ w2,
                           const float* __restrict__ w3, const float* __restrict__ w4,
                           __half* __restrict__ B1, __half* __restrict__ B2,
                           __half* __restrict__ B3, __half* __restrict__ B4)
{
    long idx = (long)blockIdx.x*blockDim.x + threadIdx.x;
    if (idx >= WC4) return;
    if (idx < WC1)      wcvt_one(w1, B1, 200, 3,   27,   32,   idx);
    else if (idx < WC2) wcvt_one(w2, B2, 400, 200, 1800, 1856, idx - WC1);
    else if (idx < WC3) wcvt_one(w3, B3, 800, 400, 3600, 3648, idx - WC2);
    else                wcvt_one(w4, B4, 10,  800, 7200, 7232, idx - WC3);
}

// layer 1 gather directly from x NCHW: fp16, Kpad=32, cols [0:27) valid
__global__ void k_gather1(const float* __restrict__ X, __half* __restrict__ A,
                          const int* __restrict__ selh, const int* __restrict__ selw)
{
    int n = blockIdx.x*blockDim.x + threadIdx.x;
    if (n >= 270592) return;
    __half row[32];
#pragma unroll
    for (int i=0;i<32;i++) row[i] = __float2half_rn(0.f);
    if (n < 270400){
        int b = n / 4225, p = n - b*4225;
        int oy = p/65, ox = p - oy*65;
        int ph = oy*2 + selh[p], pw = ox*2 + selw[p];
        const float* xb = X + (size_t)b*3*132*132 + ph*132 + pw;
#pragma unroll
        for (int ic=0; ic<3; ic++){
#pragma unroll
            for (int ky=0; ky<3; ky++){
#pragma unroll
                for (int kx=0; kx<3; kx++){
                    float v = xb[(size_t)ic*132*132 + ky*132 + kx];
                    row[(ky*3 + kx)*3 + ic] = __float2half_rn(v);
                }
            }
        }
    }
    uint4* dst = (uint4*)(A + (size_t)n*32);
    uint4* s = (uint4*)row;
#pragma unroll
    for (int i=0;i<4;i++) dst[i] = s[i];
}

// L4 combine
__global__ void k_out4(const float* __restrict__ P4, const float* __restrict__ bias,
                       float* __restrict__ out)
{
    int idx = blockIdx.x*blockDim.x + threadIdx.x;
    if (idx >= 108160) return;
    int n = idx / 10, oc = idx - n*10;
    const size_t ps = (size_t)10880*64;
    float v = P4[(size_t)n*64 + oc] + P4[ps + (size_t)n*64 + oc]
            + P4[2*ps + (size_t)n*64 + oc] + __ldg(&bias[oc]);
    int b = n / 169, p = n - b*169;
    out[(b*10 + oc)*169 + p] = v;
}

// ======================= persistent L1 GEMM (K=32, 2 ks steps) =======================
static constexpr int SMEM_L1 = 16384 * 4;

__global__ __launch_bounds__(256, 2)
void k_hmma1(const __half* __restrict__ A, const __half* __restrict__ Bw,
             const float* __restrict__ bias, const int* __restrict__ mask,
             __half* __restrict__ Out)
{
    extern __shared__ char smem[];
    const uint32_t sb = smem_u32(smem);
    const int tid = threadIdx.x, lane = tid & 31, warp = tid >> 5;
    const int wm = warp >> 1, wn = warp & 1;

    // 64B-per-row loader geometry: 512 granules = 64 rows x 4 chunks per iter (2 iters)
    const int l_row4 = tid >> 2, l_ch4 = tid & 3;            // row 0..63, ch 0..3
    const uint32_t soff4 = (uint32_t)(l_row4*128 + ((l_ch4 ^ (l_row4&7))<<4));

    // B once: rows [x*128, x*128+128) of g_B1[256][32]
    {
        const __half* Bg = Bw + (size_t)(blockIdx.x*128 + l_row4)*32 + l_ch4*8;
#pragma unroll
        for (int i=0;i<2;i++) cp16(sb + soff4 + i*8192, Bg + i*64*32);
    }

    const int NBLK = 2114, STEP = gridDim.y;
    auto loadA = [&](int it){
        int nb = blockIdx.y + it*STEP;
        if (nb >= NBLK) return;
        const __half* Ag = A + ((size_t)nb*128 + l_row4)*32 + l_ch4*8;
        uint32_t sA = sb + 16384 + (it%3)*16384;
#pragma unroll
        for (int j=0;j<2;j++) cp16(sA + soff4 + j*8192, Ag + j*64*32);
    };

    loadA(0); cp_commit();
    loadA(1); cp_commit();

    const uint32_t rowA = (uint32_t)((wm*32 + (lane & 15)) * 128);
    const uint32_t rowB = (uint32_t)((wn*64 + (lane & 15)) * 128);
    const uint32_t chbase = (uint32_t)(lane >> 4);
    const uint32_t chxor  = (uint32_t)(lane & 7);
    uint32_t aB[4];
#pragma unroll
    for (int i=0;i<4;i++) aB[i] = sb + rowB + i*16*128;

    const int niter = (NBLK - blockIdx.y + STEP - 1) / STEP;
#pragma unroll 1
    for (int it = 0; it < niter; it++){
        cp_wait1();
        __syncthreads();
        loadA(it+2); cp_commit();

        const uint32_t sA = sb + 16384 + (it%3)*16384;
        const uint32_t aA0 = sA + rowA, aA1 = aA0 + 16*128;

        float c[2][8][4];
#pragma unroll
        for (int i=0;i<2;i++)
#pragma unroll
            for (int j=0;j<8;j++)
#pragma unroll
                for (int k=0;k<4;k++) c[i][j][k] = 0.f;

        uint32_t a[2][2][4], b[2][4][4];
        {
            const uint32_t ch = (chbase ^ chxor) << 4;
            ldmx4(a[0][0], aA0 + ch); ldmx4(a[0][1], aA1 + ch);
#pragma unroll
            for (int i=0;i<4;i++) ldmx4(b[0][i], aB[i] + ch);
        }
#pragma unroll
        for (int ks = 0; ks < 2; ks++){          // K=32: 2 ks steps only
            const int cur = ks & 1, nxt = cur ^ 1;
            if (ks < 1){
                const uint32_t ch = (((ks+1)*2 + chbase) ^ chxor) << 4;
                ldmx4(a[nxt][0], aA0 + ch); ldmx4(a[nxt][1], aA1 + ch);
#pragma unroll
                for (int i=0;i<4;i++) ldmx4(b[nxt][i], aB[i] + ch);
            }
#pragma unroll
            for (int mi = 0; mi < 2; mi++)
#pragma unroll
                for (int nj = 0; nj < 8; nj++)
                    mma_fp16(c[mi][nj], a[cur][mi],
                             b[cur][nj>>1][nj&1], b[cur][nj>>1][2+(nj&1)]);
        }

        const int nb = blockIdx.y + it*STEP;
        const int gm0 = nb*128 + wm*32;
        const int oc0 = blockIdx.x*128 + wn*64;
#pragma unroll
        for (int mi = 0; mi < 2; mi++){
#pragma unroll
            for (int half = 0; half < 2; half++){
                int n = gm0 + mi*16 + half*8 + (lane >> 2);
                if (n >= 270400) continue;
                int p = n % 4225;
                int mk = mask[p];
#pragma unroll
                for (int nj = 0; nj < 8; nj++){
                    int oc = oc0 + nj*8 + (lane & 3)*2;
                    if (oc < 200){
                        float v0 = (mk ? c[mi][nj][half*2+0] : 0.f) + __ldg(&bias[oc]);
                        float v1 = (mk ? c[mi][nj][half*2+1] : 0.f) + __ldg(&bias[oc+1]);
                        v0 = fmaxf(v0, 0.f); v1 = fmaxf(v1, 0.f);
                        __half2* orow = (__half2*)(Out + (size_t)n * 200 + oc);
                        *orow = __floats2half2_rn(v0, v1);
                    }
                }
            }
        }
    }
}

// ======================= HMMA GEMM (L2/L3/L4), 8 warps, 32x64 warp tiles =======================
static constexpr int STAGE = 32768;
static constexpr int SMEM_HM = 3 * STAGE + 512 + 3712;
static constexpr int SPLITC = 38;

template <int NT, int OUTM>   // OUTM: 1=fp16 NHWC, 3=fp32 split-K partials
__global__ __launch_bounds__(256, 2)
void k_hmma(const __half* __restrict__ B,
            const float* __restrict__ bias, const int* __restrict__ mask,
            void* __restrict__ Outv,
            int Kpad, int NC, int OC, int P, int Nreal, int relu,
            const __half* __restrict__ Src, const int* __restrict__ selh,
            const int* __restrict__ selw, int IW, int ICp, int OW,
            int stride, int Klayer)
{
    extern __shared__ char smem[];
    const uint32_t sb = smem_u32(smem);
    int* s_base = (int*)(smem + 3*STAGE);
    int* s_off  = (int*)(smem + 3*STAGE + 512);
    const int tid = threadIdx.x, lane = tid & 31, warp = tid >> 5;
    const int wm = warp >> 1, wn = warp & 1;

    const long ld = (long)Kpad;
    const int l_row = tid >> 3, l_ch = tid & 7;
    const uint32_t l_soff = (uint32_t)(l_row*128 + ((l_ch ^ (l_row&7))<<4));
    const __half* Bg = B + (size_t)(blockIdx.x*NT + l_row) * ld + l_ch*8;
    const long ld32 = 32*ld;

    const int cbase = (OUTM == 3) ? (int)blockIdx.z * SPLITC : 0;
    const int NCl   = (OUTM == 3) ? min(SPLITC, NC - cbase) : NC;

    if (tid < 128){
        int n = blockIdx.y*128 + tid;
        if (n >= Nreal) n = Nreal - 1;
        int b = n / P, p = n - b*P;
        int oy = p / OW, ox = p - oy*OW;
        int ph = oy*stride + (selh ? selh[p] : 0);
        int pw = ox*stride + (selw ? selw[p] : 0);
        s_base[tid] = (b*IW + ph)*IW + pw;
    }
    for (int j = tid; j < (Klayer >> 3); j += 256){
        int k = j << 3;
        int tap = k / ICp, c = k - tap*ICp;
        int ky = tap/3, kx = tap - 3*ky;
        s_off[j] = (ky*IW + kx)*ICp + c;
    }
    __syncthreads();

    auto loadA = [&](int chunk, uint32_t sA){
        int j = chunk*8 + l_ch;
        int k = j << 3;
        uint32_t sz = (k < Klayer) ? 16u : 0u;
        long off = sz ? (long)s_off[j] : 0;
#pragma unroll
        for (int i=0;i<4;i++){
            int row = l_row + i*32;
            const __half* src = Src + (size_t)s_base[row]*ICp + off;
            cp16z(sA + l_soff + i*4096, src, sz);
        }
    };
    auto loadB = [&](int chunk, uint32_t sB){
#pragma unroll
        for (int i=0;i<NT/32;i++) cp16(sB + l_soff + i*4096, Bg + chunk*64 + i*ld32);
    };

    const uint32_t rowA = (uint32_t)((wm*32 + (lane & 15)) * 128);
    const uint32_t rowB = (uint32_t)((wn*(NT/2) + (lane & 15)) * 128);
    const uint32_t chbase = (uint32_t)(lane >> 4);
    const uint32_t chxor  = (uint32_t)(lane & 7);

    constexpr int NJ = NT/16;
    constexpr int NB = NT/32;
    float c[2][NJ][4];
#pragma unroll
    for (int i=0;i<2;i++)
#pragma unroll
        for (int j=0;j<NJ;j++)
#pragma unroll
            for (int k=0;k<4;k++) c[i][j][k] = 0.f;

    loadA(cbase, sb);       loadB(cbase, sb + 16384);       cp_commit();
    if (NCl > 1){ loadA(cbase+1, sb + STAGE); loadB(cbase+1, sb + STAGE + 16384); }
    cp_commit();

#pragma unroll 1
    for (int cc = 0; cc < NCl; cc++){
        cp_wait1();
        __syncthreads();
        if (cc + 2 < NCl){
            uint32_t sA = sb + ((cc+2) % 3)*STAGE;
            loadA(cbase+cc+2, sA); loadB(cbase+cc+2, sA + 16384);
        }
        cp_commit();

        const uint32_t sA = sb + (cc % 3)*STAGE;
        const uint32_t sB = sA + 16384;
        const uint32_t aA0 = sA + rowA, aA1 = aA0 + 16*128;
        uint32_t aB[NB];
#pragma unroll
        for (int i=0;i<NB;i++) aB[i] = sB + rowB + i*16*128;

        uint32_t a[2][2][4], b[2][NB][4];
        {
            const uint32_t ch = (chbase ^ chxor) << 4;
            ldmx4(a[0][0], aA0 + ch); ldmx4(a[0][1], aA1 + ch);
#pragma unroll
            for (int i=0;i<NB;i++) ldmx4(b[0][i], aB[i] + ch);
        }
#pragma unroll
        for (int ks = 0; ks < 4; ks++){
            const int cur = ks & 1, nxt = cur ^ 1;
            if (ks < 3){
                const uint32_t ch = (((ks+1)*2 + chbase) ^ chxor) << 4;
                ldmx4(a[nxt][0], aA0 + ch); ldmx4(a[nxt][1], aA1 + ch);
#pragma unroll
                for (int i=0;i<NB;i++) ldmx4(b[nxt][i], aB[i] + ch);
            }
#pragma unroll
            for (int mi = 0; mi < 2; mi++)
#pragma unroll
                for (int nj = 0; nj < NJ; nj++)
                    mma_fp16(c[mi][nj], a[cur][mi],
                             b[cur][nj>>1][nj&1], b[cur][nj>>1][2+(nj&1)]);
        }
    }

    const int gm0 = blockIdx.y*128 + wm*32;
    const int oc0 = blockIdx.x*NT + wn*(NT/2);
#pragma unroll
    for (int mi = 0; mi < 2; mi++){
#pragma unroll
        for (int half = 0; half < 2; half++){
            int n = gm0 + mi*16 + half*8 + (lane >> 2);
            if (n >= Nreal) continue;
            int mk = 1;
            if (OUTM != 3 && mask){ int p = n % P; mk = mask[p]; }
#pragma unroll
            for (int nj = 0; nj < NJ; nj++){
                int oc = oc0 + nj*8 + (lane & 3)*2;
                if (oc < OC || OUTM == 3){
                    if (OUTM == 3){
                        float* o = (float*)Outv + (size_t)blockIdx.z*10880*64
                                 + (size_t)n*64 + oc;
                        float2 v = {c[mi][nj][half*2+0], c[mi][nj][half*2+1]};
                        *(float2*)o = v;
                    } else {
                        float v0 = (mk ? c[mi][nj][half*2+0] : 0.f) + __ldg(&bias[oc]);
                        float v1 = (mk ? c[mi][nj][half*2+1] : 0.f) + __ldg(&bias[oc+1]);
                        if (relu){ v0 = fmaxf(v0, 0.f); v1 = fmaxf(v1, 0.f); }
                        __half2* orow = (__half2*)((__half*)Outv + (size_t)n * OC + oc);
                        *orow = __floats2half2_rn(v0, v1);
                    }
                }
            }
        }
    }
}

// ======================= launch =======================
extern "C" void kernel_launch(void* const* d_in, const int* in_sizes, int n_in,
                              void* d_out, int out_size) {
    const float* x     = (const float*)d_in[0];
    const float* w1    = (const float*)d_in[1];
    const float* b1    = (const float*)d_in[2];
    const float* w2    = (const float*)d_in[3];
    const float* b2    = (const float*)d_in[4];
    const float* w3    = (const float*)d_in[5];
    const float* b3    = (const float*)d_in[6];
    const float* w4    = (const float*)d_in[7];
    const float* b4    = (const float*)d_in[8];
    const int*   selh1 = (const int*)d_in[9];
    const int*   selw1 = (const int*)d_in[10];
    const int*   mask1 = (const int*)d_in[11];
    const int*   selh2 = (const int*)d_in[12];
    const int*   selw2 = (const int*)d_in[13];
    const int*   mask2 = (const int*)d_in[14];
    const int*   selh3 = (const int*)d_in[15];
    const int*   selw3 = (const int*)d_in[16];
    const int*   mask3 = (const int*)d_in[17];

    float *pP4;
    __half *pO1, *pO2, *pO3, *pA1, *pB1, *pB2, *pB3, *pB4;
    cudaGetSymbolAddress((void**)&pO1, g_O1);
    cudaGetSymbolAddress((void**)&pO2, g_O2);
    cudaGetSymbolAddress((void**)&pO3, g_O3);
    cudaGetSymbolAddress((void**)&pP4, g_P4);
    cudaGetSymbolAddress((void**)&pA1, g_A1);
    cudaGetSymbolAddress((void**)&pB1, g_B1);
    cudaGetSymbolAddress((void**)&pB2, g_B2);
    cudaGetSymbolAddress((void**)&pB3, g_B3);
    cudaGetSymbolAddress((void**)&pB4, g_B4);

    cudaFuncSetAttribute((const void*)k_hmma1,
                         cudaFuncAttributeMaxDynamicSharedMemorySize, SMEM_L1);
    cudaFuncSetAttribute((const void*)k_hmma<128,1>,
                         cudaFuncAttributeMaxDynamicSharedMemorySize, SMEM_HM);
    cudaFuncSetAttribute((const void*)k_hmma<64,3>,
                         cudaFuncAttributeMaxDynamicSharedMemorySize, SMEM_HM);

    // ---- all weight conversions in ONE launch + L1 gather ----
    k_wcvt_all<<<(unsigned)((WC4 + 255) / 256), 256>>>(w1, w2, w3, w4,
                                                       pB1, pB2, pB3, pB4);
    k_gather1<<<(270592 + 255) / 256, 256>>>(x, pA1, selh1, selw1);

    // ---- layer 1: persistent-B GEMM, K=32 ----
    k_hmma1<<<dim3(2, 148), 256, SMEM_L1>>>(pA1, pB1, b1, mask1, pO1);

    // ---- layer 2: fused gather GEMM, K=1800, Kpad=1856, NC=29, fp16 out ----
    k_hmma<128,1><<<dim3(4, 482), 256, SMEM_HM>>>(
        pB2, b2, mask2, pO2, 1856, 29, 400, 961, 61504, 1,
        pO1, selh2, selw2, 65, 200, 31, 2, 1800);

    // ---- layer 3: fused gather GEMM, K=3600, Kpad=3648, NC=57, fp16 out ----
    k_hmma<128,1><<<dim3(7, 114), 256, SMEM_HM>>>(
        pB3, b3, mask3, pO3, 3648, 57, 800, 225, 14400, 1,
        pO2, selh3, selw3, 31, 400, 15, 2, 3600);

    // ---- layer 4: fused dense GEMM, split-K x3 partials + combine ----
    k_hmma<64,3><<<dim3(1, 85, 3), 256, SMEM_HM>>>(
        pB4, b4, nullptr, pP4, 7232, 113, 10, 169, 10816, 0,
        pO3, nullptr, nullptr, 15, 800, 13, 1, 7200);
    k_out4<<<(108160 + 255) / 256, 256>>>(pP4, b4, (float*)d_out);
}

// round 15
// speedup vs baseline: 1.1089x; 1.0366x over previous
#include <cuda_runtime.h>
#include <cuda_fp16.h>
#include <cstdint>

#define DINLINE __device__ __forceinline__

// ======================= scratch (device globals) =======================
__device__ __align__(16) __half g_O1[(size_t)64*65*65*200]; // L1 out fp16 NHWC
__device__ __align__(16) __half g_O2[(size_t)64*31*31*400]; // L2 out fp16 NHWC
__device__ __align__(16) __half g_O3[(size_t)64*15*15*800]; // L3 out fp16 NHWC
__device__ __align__(16) float  g_P4[(size_t)3*10880*64];   // L4 split-K partials

// L1 im2col: A1[Npad=270592][32]
__device__ __align__(16) __half g_A1[(size_t)270592*32];
// weights fp16 [OCpad][Kpad]
__device__ __align__(16) __half g_B1[(size_t)256*32];
__device__ __align__(16) __half g_B2[(size_t)512*1856];
__device__ __align__(16) __half g_B3[(size_t)896*3648];
__device__ __align__(16) __half g_B4[(size_t)64*7232];

// ======================= helpers =======================
DINLINE uint32_t smem_u32(const void* p){
    uint32_t a;
    asm("{ .reg .u64 t; cvta.to.shared.u64 t, %1; cvt.u32.u64 %0, t; }" : "=r"(a) : "l"(p));
    return a;
}
DINLINE void cp16(uint32_t dst, const void* src){
    asm volatile("cp.async.cg.shared.global [%0], [%1], 16;" :: "r"(dst), "l"(src));
}
DINLINE void cp16z(uint32_t dst, const void* src, uint32_t srcsize){
    asm volatile("cp.async.cg.shared.global [%0], [%1], 16, %2;" :: "r"(dst), "l"(src), "r"(srcsize));
}
DINLINE void cp_commit(){ asm volatile("cp.async.commit_group;" ::: "memory"); }
DINLINE void cp_wait1(){ asm volatile("cp.async.wait_group 1;" ::: "memory"); }

DINLINE void ldmx4(uint32_t r[4], uint32_t addr){
    asm volatile("ldmatrix.sync.aligned.m8n8.x4.shared.b16 {%0,%1,%2,%3}, [%4];"
        : "=r"(r[0]), "=r"(r[1]), "=r"(r[2]), "=r"(r[3]) : "r"(addr));
}
DINLINE void mma_fp16(float c[4], const uint32_t a[4], uint32_t b0, uint32_t b1){
    asm volatile("mma.sync.aligned.m16n8k16.row.col.f32.f16.f16.f32 "
        "{%0,%1,%2,%3}, {%4,%5,%6,%7}, {%8,%9}, {%0,%1,%2,%3};"
        : "+f"(c[0]), "+f"(c[1]), "+f"(c[2]), "+f"(c[3])
        : "r"(a[0]), "r"(a[1]), "r"(a[2]), "r"(a[3]), "r"(b0), "r"(b1));
}

// ======================= transforms =======================
DINLINE void wcvt_one(const float* W, __half* Bw, int OC, int IC, int Klayer,
                      int Kpad, long idx)
{
    int oc = (int)(idx / Kpad);
    int kk = (int)(idx - (long)oc*Kpad);
    __half out = __float2half_rn(0.f);
    if (oc < OC && kk < Klayer){
        int tap = kk/IC, c = kk - tap*IC;
        out = __float2half_rn(W[((size_t)oc*IC + c)*9 + tap]);
    }
    Bw[idx] = out;
}

static constexpr long WC1 = (long)256*32;
static constexpr long WC2 = WC1 + (long)512*1856;
static constexpr long WC3 = WC2 + (long)896*3648;
static constexpr long WC4 = WC3 + (long)64*7232;

__global__ void k_wcvt_all(const float* __restrict__ w1, const float* __restrict__ w2,
                           const float* __restrict__ w3, const float* __restrict__ w4,
                           __half* __restrict__ B1, __half* __restrict__ B2,
                           __half* __restrict__ B3, __half* __restrict__ B4)
{
    long idx = (long)blockIdx.x*blockDim.x + threadIdx.x;
    if (idx >= WC4) return;
    if (idx < WC1)      wcvt_one(w1, B1, 200, 3,   27,   32,   idx);
    else if (idx < WC2) wcvt_one(w2, B2, 400, 200, 1800, 1856, idx - WC1);
    else if (idx < WC3) wcvt_one(w3, B3, 800, 400, 3600, 3648, idx - WC2);
    else                wcvt_one(w4, B4, 10,  800, 7200, 7232, idx - WC3);
}

// layer 1 gather from x NCHW: fp16, Kpad=32, cols [0:27) valid
__global__ void k_gather1(const float* __restrict__ X, __half* __restrict__ A,
                          const int* __restrict__ selh, const int* __restrict__ selw)
{
    int n = blockIdx.x*blockDim.x + threadIdx.x;
    if (n >= 270592) return;
    __half row[32];
#pragma unroll
    for (int i=0;i<32;i++) row[i] = __float2half_rn(0.f);
    if (n < 270400){
        int b = n / 4225, p = n - b*4225;
        int oy = p/65, ox = p - oy*65;
        int ph = oy*2 + selh[p], pw = ox*2 + selw[p];
        const float* xb = X + (size_t)b*3*132*132 + ph*132 + pw;
#pragma unroll
        for (int ic=0; ic<3; ic++){
#pragma unroll
            for (int ky=0; ky<3; ky++){
#pragma unroll
                for (int kx=0; kx<3; kx++){
                    float v = xb[(size_t)ic*132*132 + ky*132 + kx];
                    row[(ky*3 + kx)*3 + ic] = __float2half_rn(v);
                }
            }
        }
    }
    uint4* dst = (uint4*)(A + (size_t)n*32);
    uint4* s = (uint4*)row;
#pragma unroll
    for (int i=0;i<4;i++) dst[i] = s[i];
}

// L4 combine
__global__ void k_out4(const float* __restrict__ P4, const float* __restrict__ bias,
                       float* __restrict__ out)
{
    int idx = blockIdx.x*blockDim.x + threadIdx.x;
    if (idx >= 108160) return;
    int n = idx / 10, oc = idx - n*10;
    const size_t ps = (size_t)10880*64;
    float v = P4[(size_t)n*64 + oc] + P4[ps + (size_t)n*64 + oc]
            + P4[2*ps + (size_t)n*64 + oc] + __ldg(&bias[oc]);
    int b = n / 169, p = n - b*169;
    out[(b*10 + oc)*169 + p] = v;
}

// ======================= persistent L1 GEMM (K=32, 2 ks steps) =======================
static constexpr int SMEM_L1 = 16384 * 4;

__global__ __launch_bounds__(256, 2)
void k_hmma1(const __half* __restrict__ A, const __half* __restrict__ Bw,
             const float* __restrict__ bias, const int* __restrict__ mask,
             __half* __restrict__ Out)
{
    extern __shared__ char smem[];
    const uint32_t sb = smem_u32(smem);
    const int tid = threadIdx.x, lane = tid & 31, warp = tid >> 5;
    const int wm = warp >> 1, wn = warp & 1;

    const int l_row4 = tid >> 2, l_ch4 = tid & 3;
    const uint32_t soff4 = (uint32_t)(l_row4*128 + ((l_ch4 ^ (l_row4&7))<<4));

    {
        const __half* Bg = Bw + (size_t)(blockIdx.x*128 + l_row4)*32 + l_ch4*8;
#pragma unroll
        for (int i=0;i<2;i++) cp16(sb + soff4 + i*8192, Bg + i*64*32);
    }

    const int NBLK = 2114, STEP = gridDim.y;
    auto loadA = [&](int it){
        int nb = blockIdx.y + it*STEP;
        if (nb >= NBLK) return;
        const __half* Ag = A + ((size_t)nb*128 + l_row4)*32 + l_ch4*8;
        uint32_t sA = sb + 16384 + (it%3)*16384;
#pragma unroll
        for (int j=0;j<2;j++) cp16(sA + soff4 + j*8192, Ag + j*64*32);
    };

    loadA(0); cp_commit();
    loadA(1); cp_commit();

    const uint32_t rowA = (uint32_t)((wm*32 + (lane & 15)) * 128);
    const uint32_t rowB = (uint32_t)((wn*64 + (lane & 15)) * 128);
    const uint32_t chbase = (uint32_t)(lane >> 4);
    const uint32_t chxor  = (uint32_t)(lane & 7);
    uint32_t aB[4];
#pragma unroll
    for (int i=0;i<4;i++) aB[i] = sb + rowB + i*16*128;

    const int niter = (NBLK - blockIdx.y + STEP - 1) / STEP;
#pragma unroll 1
    for (int it = 0; it < niter; it++){
        cp_wait1();
        __syncthreads();
        loadA(it+2); cp_commit();

        const uint32_t sA = sb + 16384 + (it%3)*16384;
        const uint32_t aA0 = sA + rowA, aA1 = aA0 + 16*128;

        float c[2][8][4];
#pragma unroll
        for (int i=0;i<2;i++)
#pragma unroll
            for (int j=0;j<8;j++)
#pragma unroll
                for (int k=0;k<4;k++) c[i][j][k] = 0.f;

        uint32_t a[2][2][4], b[2][4][4];
        {
            const uint32_t ch = (chbase ^ chxor) << 4;
            ldmx4(a[0][0], aA0 + ch); ldmx4(a[0][1], aA1 + ch);
#pragma unroll
            for (int i=0;i<4;i++) ldmx4(b[0][i], aB[i] + ch);
        }
#pragma unroll
        for (int ks = 0; ks < 2; ks++){
            const int cur = ks & 1, nxt = cur ^ 1;
            if (ks < 1){
                const uint32_t ch = (((ks+1)*2 + chbase) ^ chxor) << 4;
                ldmx4(a[nxt][0], aA0 + ch); ldmx4(a[nxt][1], aA1 + ch);
#pragma unroll
                for (int i=0;i<4;i++) ldmx4(b[nxt][i], aB[i] + ch);
            }
#pragma unroll
            for (int mi = 0; mi < 2; mi++)
#pragma unroll
                for (int nj = 0; nj < 8; nj++)
                    mma_fp16(c[mi][nj], a[cur][mi],
                             b[cur][nj>>1][nj&1], b[cur][nj>>1][2+(nj&1)]);
        }

        const int nb = blockIdx.y + it*STEP;
        const int gm0 = nb*128 + wm*32;
        const int oc0 = blockIdx.x*128 + wn*64;
#pragma unroll
        for (int mi = 0; mi < 2; mi++){
#pragma unroll
            for (int half = 0; half < 2; half++){
                int n = gm0 + mi*16 + half*8 + (lane >> 2);
                if (n >= 270400) continue;
                int p = n % 4225;
                int mk = mask[p];
#pragma unroll
                for (int nj = 0; nj < 8; nj++){
                    int oc = oc0 + nj*8 + (lane & 3)*2;
                    if (oc < 200){
                        float v0 = (mk ? c[mi][nj][half*2+0] : 0.f) + __ldg(&bias[oc]);
                        float v1 = (mk ? c[mi][nj][half*2+1] : 0.f) + __ldg(&bias[oc+1]);
                        v0 = fmaxf(v0, 0.f); v1 = fmaxf(v1, 0.f);
                        __half2* orow = (__half2*)(Out + (size_t)n * 200 + oc);
                        *orow = __floats2half2_rn(v0, v1);
                    }
                }
            }
        }
    }
}

// ======================= HMMA GEMM (L2/L3/L4), 8 warps, 32 x (NT/2) warp tiles =======================
static constexpr int STAGE = 32768;
static constexpr int SMEM_HM = 3 * STAGE + 512 + 3712;
static constexpr int SPLITC = 38;

template <int NT, int OUTM>   // OUTM: 1=fp16 NHWC, 3=fp32 split-K partials
__global__ __launch_bounds__(256, 2)
void k_hmma(const __half* __restrict__ B,
            const float* __restrict__ bias, const int* __restrict__ mask,
            void* __restrict__ Outv,
            int oc_base, int Kpad, int NC, int OC, int P, int Nreal, int relu,
            const __half* __restrict__ Src, const int* __restrict__ selh,
            const int* __restrict__ selw, int IW, int ICp, int OW,
            int stride, int Klayer)
{
    extern __shared__ char smem[];
    const uint32_t sb = smem_u32(smem);
    int* s_base = (int*)(smem + 3*STAGE);
    int* s_off  = (int*)(smem + 3*STAGE + 512);
    const int tid = threadIdx.x, lane = tid & 31, warp = tid >> 5;
    const int wm = warp >> 1, wn = warp & 1;

    const long ld = (long)Kpad;
    const int l_row = tid >> 3, l_ch = tid & 7;
    const uint32_t l_soff = (uint32_t)(l_row*128 + ((l_ch ^ (l_row&7))<<4));
    const __half* Bg = B + (size_t)(oc_base + blockIdx.x*NT + l_row) * ld + l_ch*8;
    const long ld32 = 32*ld;

    const int cbase = (OUTM == 3) ? (int)blockIdx.z * SPLITC : 0;
    const int NCl   = (OUTM == 3) ? min(SPLITC, NC - cbase) : NC;

    if (tid < 128){
        int n = blockIdx.y*128 + tid;
        if (n >= Nreal) n = Nreal - 1;
        int b = n / P, p = n - b*P;
        int oy = p / OW, ox = p - oy*OW;
        int ph = oy*stride + (selh ? selh[p] : 0);
        int pw = ox*stride + (selw ? selw[p] : 0);
        s_base[tid] = (b*IW + ph)*IW + pw;
    }
    for (int j = tid; j < (Klayer >> 3); j += 256){
        int k = j << 3;
        int tap = k / ICp, c = k - tap*ICp;
        int ky = tap/3, kx = tap - 3*ky;
        s_off[j] = (ky*IW + kx)*ICp + c;
    }
    __syncthreads();

    auto loadA = [&](int chunk, uint32_t sA){
        int j = chunk*8 + l_ch;
        int k = j << 3;
        uint32_t sz = (k < Klayer) ? 16u : 0u;
        long off = sz ? (long)s_off[j] : 0;
#pragma unroll
        for (int i=0;i<4;i++){
            int row = l_row + i*32;
            const __half* src = Src + (size_t)s_base[row]*ICp + off;
            cp16z(sA + l_soff + i*4096, src, sz);
        }
    };
    auto loadB = [&](int chunk, uint32_t sB){
#pragma unroll
        for (int i=0;i<NT/32;i++) cp16(sB + l_soff + i*4096, Bg + chunk*64 + i*ld32);
    };

    const uint32_t rowA = (uint32_t)((wm*32 + (lane & 15)) * 128);
    const uint32_t rowB = (uint32_t)((wn*(NT/2) + (lane & 15)) * 128);
    const uint32_t chbase = (uint32_t)(lane >> 4);
    const uint32_t chxor  = (uint32_t)(lane & 7);

    constexpr int NJ = NT/16;
    constexpr int NB = (NT >= 64) ? NT/32 : 1;
    float c[2][NJ][4];
#pragma unroll
    for (int i=0;i<2;i++)
#pragma unroll
        for (int j=0;j<NJ;j++)
#pragma unroll
            for (int k=0;k<4;k++) c[i][j][k] = 0.f;

    loadA(cbase, sb);       loadB(cbase, sb + 16384);       cp_commit();
    if (NCl > 1){ loadA(cbase+1, sb + STAGE); loadB(cbase+1, sb + STAGE + 16384); }
    cp_commit();

#pragma unroll 1
    for (int cc = 0; cc < NCl; cc++){
        cp_wait1();
        __syncthreads();
        if (cc + 2 < NCl){
            uint32_t sA = sb + ((cc+2) % 3)*STAGE;
            loadA(cbase+cc+2, sA); loadB(cbase+cc+2, sA + 16384);
        }
        cp_commit();

        const uint32_t sA = sb + (cc % 3)*STAGE;
        const uint32_t sB = sA + 16384;
        const uint32_t aA0 = sA + rowA, aA1 = aA0 + 16*128;
        uint32_t aB[NB];
#pragma unroll
        for (int i=0;i<NB;i++) aB[i] = sB + rowB + i*16*128;

        uint32_t a[2][2][4], b[2][NB][4];
        {
            const uint32_t ch = (chbase ^ chxor) << 4;
            ldmx4(a[0][0], aA0 + ch); ldmx4(a[0][1], aA1 + ch);
#pragma unroll
            for (int i=0;i<NB;i++) ldmx4(b[0][i], aB[i] + ch);
        }
#pragma unroll
        for (int ks = 0; ks < 4; ks++){
            const int cur = ks & 1, nxt = cur ^ 1;
            if (ks < 3){
                const uint32_t ch = (((ks+1)*2 + chbase) ^ chxor) << 4;
                ldmx4(a[nxt][0], aA0 + ch); ldmx4(a[nxt][1], aA1 + ch);
#pragma unroll
                for (int i=0;i<NB;i++) ldmx4(b[nxt][i], aB[i] + ch);
            }
#pragma unroll
            for (int mi = 0; mi < 2; mi++)
#pragma unroll
                for (int nj = 0; nj < NJ; nj++)
                    mma_fp16(c[mi][nj], a[cur][mi],
                             b[cur][(NJ>2)?(nj>>1):0][nj&1],
                             b[cur][(NJ>2)?(nj>>1):0][2+(nj&1)]);
        }
    }

    const int gm0 = blockIdx.y*128 + wm*32;
    const int oc0 = oc_base + blockIdx.x*NT + wn*(NT/2);
#pragma unroll
    for (int mi = 0; mi < 2; mi++){
#pragma unroll
        for (int half = 0; half < 2; half++){
            int n = gm0 + mi*16 + half*8 + (lane >> 2);
            if (n >= Nreal) continue;
            int mk = 1;
            if (OUTM != 3 && mask){ int p = n % P; mk = mask[p]; }
#pragma unroll
            for (int nj = 0; nj < NJ; nj++){
                int oc = oc0 + nj*8 + (lane & 3)*2;
                if (oc < OC || OUTM == 3){
                    if (OUTM == 3){
                        float* o = (float*)Outv + (size_t)blockIdx.z*10880*64
                                 + (size_t)n*64 + oc;
                        float2 v = {c[mi][nj][half*2+0], c[mi][nj][half*2+1]};
                        *(float2*)o = v;
                    } else {
                        float v0 = (mk ? c[mi][nj][half*2+0] : 0.f) + __ldg(&bias[oc]);
                        float v1 = (mk ? c[mi][nj][half*2+1] : 0.f) + __ldg(&bias[oc+1]);
                        if (relu){ v0 = fmaxf(v0, 0.f); v1 = fmaxf(v1, 0.f); }
                        __half2* orow = (__half2*)((__half*)Outv + (size_t)n * OC + oc);
                        *orow = __floats2half2_rn(v0, v1);
                    }
                }
            }
        }
    }
}

// ======================= launch =======================
extern "C" void kernel_launch(void* const* d_in, const int* in_sizes, int n_in,
                              void* d_out, int out_size) {
    const float* x     = (const float*)d_in[0];
    const float* w1    = (const float*)d_in[1];
    const float* b1    = (const float*)d_in[2];
    const float* w2    = (const float*)d_in[3];
    const float* b2    = (const float*)d_in[4];
    const float* w3    = (const float*)d_in[5];
    const float* b3    = (const float*)d_in[6];
    const float* w4    = (const float*)d_in[7];
    const float* b4    = (const float*)d_in[8];
    const int*   selh1 = (const int*)d_in[9];
    const int*   selw1 = (const int*)d_in[10];
    const int*   mask1 = (const int*)d_in[11];
    const int*   selh2 = (const int*)d_in[12];
    const int*   selw2 = (const int*)d_in[13];
    const int*   mask2 = (const int*)d_in[14];
    const int*   selh3 = (const int*)d_in[15];
    const int*   selw3 = (const int*)d_in[16];
    const int*   mask3 = (const int*)d_in[17];

    float *pP4;
    __half *pO1, *pO2, *pO3, *pA1, *pB1, *pB2, *pB3, *pB4;
    cudaGetSymbolAddress((void**)&pO1, g_O1);
    cudaGetSymbolAddress((void**)&pO2, g_O2);
    cudaGetSymbolAddress((void**)&pO3, g_O3);
    cudaGetSymbolAddress((void**)&pP4, g_P4);
    cudaGetSymbolAddress((void**)&pA1, g_A1);
    cudaGetSymbolAddress((void**)&pB1, g_B1);
    cudaGetSymbolAddress((void**)&pB2, g_B2);
    cudaGetSymbolAddress((void**)&pB3, g_B3);
    cudaGetSymbolAddress((void**)&pB4, g_B4);

    cudaFuncSetAttribute((const void*)k_hmma1,
                         cudaFuncAttributeMaxDynamicSharedMemorySize, SMEM_L1);
    cudaFuncSetAttribute((const void*)k_hmma<128,1>,
                         cudaFuncAttributeMaxDynamicSharedMemorySize, SMEM_HM);
    cudaFuncSetAttribute((const void*)k_hmma<32,1>,
                         cudaFuncAttributeMaxDynamicSharedMemorySize, SMEM_HM);
    cudaFuncSetAttribute((const void*)k_hmma<64,3>,
                         cudaFuncAttributeMaxDynamicSharedMemorySize, SMEM_HM);

    // ---- all weight conversions in ONE launch + L1 gather ----
    k_wcvt_all<<<(unsigned)((WC4 + 255) / 256), 256>>>(w1, w2, w3, w4,
                                                       pB1, pB2, pB3, pB4);
    k_gather1<<<(270592 + 255) / 256, 256>>>(x, pA1, selh1, selw1);

    // ---- layer 1: persistent-B GEMM, K=32 ----
    k_hmma1<<<dim3(2, 148), 256, SMEM_L1>>>(pA1, pB1, b1, mask1, pO1);

    // ---- layer 2: fused gather GEMM, oc 0..383 (NT=128) + 384..399 (NT=32) ----
    k_hmma<128,1><<<dim3(3, 482), 256, SMEM_HM>>>(
        pB2, b2, mask2, pO2, 0, 1856, 29, 400, 961, 61504, 1,
        pO1, selh2, selw2, 65, 200, 31, 2, 1800);
    k_hmma<32,1><<<dim3(1, 482), 256, SMEM_HM>>>(
        pB2, b2, mask2, pO2, 384, 1856, 29, 400, 961, 61504, 1,
        pO1, selh2, selw2, 65, 200, 31, 2, 1800);

    // ---- layer 3: fused gather GEMM, oc 0..767 (NT=128) + 768..799 (NT=32) ----
    k_hmma<128,1><<<dim3(6, 114), 256, SMEM_HM>>>(
        pB3, b3, mask3, pO3, 0, 3648, 57, 800, 225, 14400, 1,
        pO2, selh3, selw3, 31, 400, 15, 2, 3600);
    k_hmma<32,1><<<dim3(1, 114), 256, SMEM_HM>>>(
        pB3, b3, mask3, pO3, 768, 3648, 57, 800, 225, 14400, 1,
        pO2, selh3, selw3, 31, 400, 15, 2, 3600);

    // ---- layer 4: fused dense GEMM, split-K x3 partials + combine ----
    k_hmma<64,3><<<dim3(1, 85, 3), 256, SMEM_HM>>>(
        pB4, b4, nullptr, pP4, 0, 7232, 113, 10, 169, 10816, 0,
        pO3, nullptr, nullptr, 15, 800, 13, 1, 7200);
    k_out4<<<(108160 + 255) / 256, 256>>>(pP4, b4, (float*)d_out);
}

// round 16
// speedup vs baseline: 1.1687x; 1.0538x over previous
#include <cuda_runtime.h>
#include <cuda_fp16.h>
#include <cstdint>

#define DINLINE __device__ __forceinline__

// ======================= scratch (device globals) =======================
__device__ __align__(16) __half g_O1[(size_t)64*65*65*200];
__device__ __align__(16) __half g_O2[(size_t)64*31*31*400];
__device__ __align__(16) __half g_O3[(size_t)64*15*15*800];
__device__ __align__(16) float  g_P4[(size_t)3*10880*32];   // L4 split-K partials

__device__ __align__(16) __half g_A1[(size_t)270592*32];
__device__ __align__(16) __half g_B1[(size_t)256*32];
__device__ __align__(16) __half g_B2[(size_t)512*1856];
__device__ __align__(16) __half g_B3[(size_t)896*3648];
__device__ __align__(16) __half g_B4[(size_t)64*7232];

// ======================= helpers =======================
DINLINE uint32_t smem_u32(const void* p){
    uint32_t a;
    asm("{ .reg .u64 t; cvta.to.shared.u64 t, %1; cvt.u32.u64 %0, t; }" : "=r"(a) : "l"(p));
    return a;
}
DINLINE void cp16(uint32_t dst, const void* src){
    asm volatile("cp.async.cg.shared.global [%0], [%1], 16;" :: "r"(dst), "l"(src));
}
DINLINE void cp16z(uint32_t dst, const void* src, uint32_t srcsize){
    asm volatile("cp.async.cg.shared.global [%0], [%1], 16, %2;" :: "r"(dst), "l"(src), "r"(srcsize));
}
DINLINE void cp_commit(){ asm volatile("cp.async.commit_group;" ::: "memory"); }
DINLINE void cp_wait1(){ asm volatile("cp.async.wait_group 1;" ::: "memory"); }

DINLINE void ldmx4(uint32_t r[4], uint32_t addr){
    asm volatile("ldmatrix.sync.aligned.m8n8.x4.shared.b16 {%0,%1,%2,%3}, [%4];"
        : "=r"(r[0]), "=r"(r[1]), "=r"(r[2]), "=r"(r[3]) : "r"(addr));
}
DINLINE void mma_fp16(float c[4], const uint32_t a[4], uint32_t b0, uint32_t b1){
    asm volatile("mma.sync.aligned.m16n8k16.row.col.f32.f16.f16.f32 "
        "{%0,%1,%2,%3}, {%4,%5,%6,%7}, {%8,%9}, {%0,%1,%2,%3};"
        : "+f"(c[0]), "+f"(c[1]), "+f"(c[2]), "+f"(c[3])
        : "r"(a[0]), "r"(a[1]), "r"(a[2]), "r"(a[3]), "r"(b0), "r"(b1));
}

// ======================= transforms =======================
DINLINE void wcvt_one(const float* W, __half* Bw, int OC, int IC, int Klayer,
                      int Kpad, long idx)
{
    int oc = (int)(idx / Kpad);
    int kk = (int)(idx - (long)oc*Kpad);
    __half out = __float2half_rn(0.f);
    if (oc < OC && kk < Klayer){
        int tap = kk/IC, c = kk - tap*IC;
        out = __float2half_rn(W[((size_t)oc*IC + c)*9 + tap]);
    }
    Bw[idx] = out;
}

static constexpr long WC1 = (long)256*32;
static constexpr long WC2 = WC1 + (long)512*1856;
static constexpr long WC3 = WC2 + (long)896*3648;
static constexpr long WC4 = WC3 + (long)64*7232;

__global__ void k_wcvt_all(const float* __restrict__ w1, const float* __restrict__ w2,
                           const float* __restrict__ w3, const float* __restrict__ w4,
                           __half* __restrict__ B1, __half* __restrict__ B2,
                           __half* __restrict__ B3, __half* __restrict__ B4)
{
    long idx = (long)blockIdx.x*blockDim.x + threadIdx.x;
    if (idx >= WC4) return;
    if (idx < WC1)      wcvt_one(w1, B1, 200, 3,   27,   32,   idx);
    else if (idx < WC2) wcvt_one(w2, B2, 400, 200, 1800, 1856, idx - WC1);
    else if (idx < WC3) wcvt_one(w3, B3, 800, 400, 3600, 3648, idx - WC2);
    else                wcvt_one(w4, B4, 10,  800, 7200, 7232, idx - WC3);
}

__global__ void k_gather1(const float* __restrict__ X, __half* __restrict__ A,
                          const int* __restrict__ selh, const int* __restrict__ selw)
{
    int n = blockIdx.x*blockDim.x + threadIdx.x;
    if (n >= 270592) return;
    __half row[32];
#pragma unroll
    for (int i=0;i<32;i++) row[i] = __float2half_rn(0.f);
    if (n < 270400){
        int b = n / 4225, p = n - b*4225;
        int oy = p/65, ox = p - oy*65;
        int ph = oy*2 + selh[p], pw = ox*2 + selw[p];
        const float* xb = X + (size_t)b*3*132*132 + ph*132 + pw;
#pragma unroll
        for (int ic=0; ic<3; ic++)
#pragma unroll
            for (int ky=0; ky<3; ky++)
#pragma unroll
                for (int kx=0; kx<3; kx++)
                    row[(ky*3 + kx)*3 + ic] =
                        __float2half_rn(xb[(size_t)ic*132*132 + ky*132 + kx]);
    }
    uint4* dst = (uint4*)(A + (size_t)n*32);
    uint4* s = (uint4*)row;
#pragma unroll
    for (int i=0;i<4;i++) dst[i] = s[i];
}

__global__ void k_out4(const float* __restrict__ P4, const float* __restrict__ bias,
                       float* __restrict__ out)
{
    int idx = blockIdx.x*blockDim.x + threadIdx.x;
    if (idx >= 108160) return;
    int n = idx / 10, oc = idx - n*10;
    const size_t ps = (size_t)10880*32;
    float v = P4[(size_t)n*32 + oc] + P4[ps + (size_t)n*32 + oc]
            + P4[2*ps + (size_t)n*32 + oc] + __ldg(&bias[oc]);
    int b = n / 169, p = n - b*169;
    out[(b*10 + oc)*169 + p] = v;
}

// ======================= persistent L1 GEMM (K=32) =======================
static constexpr int SMEM_L1 = 16384 * 4;

__global__ __launch_bounds__(256, 2)
void k_hmma1(const __half* __restrict__ A, const __half* __restrict__ Bw,
             const float* __restrict__ bias, const int* __restrict__ mask,
             __half* __restrict__ Out)
{
    extern __shared__ char smem[];
    const uint32_t sb = smem_u32(smem);
    const int tid = threadIdx.x, lane = tid & 31, warp = tid >> 5;
    const int wm = warp >> 1, wn = warp & 1;

    const int l_row4 = tid >> 2, l_ch4 = tid & 3;
    const uint32_t soff4 = (uint32_t)(l_row4*128 + ((l_ch4 ^ (l_row4&7))<<4));

    {
        const __half* Bg = Bw + (size_t)(blockIdx.x*128 + l_row4)*32 + l_ch4*8;
#pragma unroll
        for (int i=0;i<2;i++) cp16(sb + soff4 + i*8192, Bg + i*64*32);
    }

    const int NBLK = 2114, STEP = gridDim.y;
    auto loadA = [&](int it){
        int nb = blockIdx.y + it*STEP;
        if (nb >= NBLK) return;
        const __half* Ag = A + ((size_t)nb*128 + l_row4)*32 + l_ch4*8;
        uint32_t sA = sb + 16384 + (it%3)*16384;
#pragma unroll
        for (int j=0;j<2;j++) cp16(sA + soff4 + j*8192, Ag + j*64*32);
    };

    loadA(0); cp_commit();
    loadA(1); cp_commit();

    const uint32_t rowA = (uint32_t)((wm*32 + (lane & 15)) * 128);
    const uint32_t rowB = (uint32_t)((wn*64 + (lane & 15)) * 128);
    const uint32_t chbase = (uint32_t)(lane >> 4);
    const uint32_t chxor  = (uint32_t)(lane & 7);
    uint32_t aB[4];
#pragma unroll
    for (int i=0;i<4;i++) aB[i] = sb + rowB + i*16*128;

    const int niter = (NBLK - blockIdx.y + STEP - 1) / STEP;
#pragma unroll 1
    for (int it = 0; it < niter; it++){
        cp_wait1();
        __syncthreads();
        loadA(it+2); cp_commit();

        const uint32_t sA = sb + 16384 + (it%3)*16384;
        const uint32_t aA0 = sA + rowA, aA1 = aA0 + 16*128;

        float c[2][8][4];
#pragma unroll
        for (int i=0;i<2;i++)
#pragma unroll
            for (int j=0;j<8;j++)
#pragma unroll
                for (int k=0;k<4;k++) c[i][j][k] = 0.f;

        uint32_t a[2][2][4], b[2][4][4];
        {
            const uint32_t ch = (chbase ^ chxor) << 4;
            ldmx4(a[0][0], aA0 + ch); ldmx4(a[0][1], aA1 + ch);
#pragma unroll
            for (int i=0;i<4;i++) ldmx4(b[0][i], aB[i] + ch);
        }
#pragma unroll
        for (int ks = 0; ks < 2; ks++){
            const int cur = ks & 1, nxt = cur ^ 1;
            if (ks < 1){
                const uint32_t ch = (((ks+1)*2 + chbase) ^ chxor) << 4;
                ldmx4(a[nxt][0], aA0 + ch); ldmx4(a[nxt][1], aA1 + ch);
#pragma unroll
                for (int i=0;i<4;i++) ldmx4(b[nxt][i], aB[i] + ch);
            }
#pragma unroll
            for (int mi = 0; mi < 2; mi++)
#pragma unroll
                for (int nj = 0; nj < 8; nj++)
                    mma_fp16(c[mi][nj], a[cur][mi],
                             b[cur][nj>>1][nj&1], b[cur][nj>>1][2+(nj&1)]);
        }

        const int nb = blockIdx.y + it*STEP;
        const int gm0 = nb*128 + wm*32;
        const int oc0 = blockIdx.x*128 + wn*64;
#pragma unroll
        for (int mi = 0; mi < 2; mi++){
#pragma unroll
            for (int half = 0; half < 2; half++){
                int n = gm0 + mi*16 + half*8 + (lane >> 2);
                if (n >= 270400) continue;
                int p = n % 4225;
                int mk = mask[p];
#pragma unroll
                for (int nj = 0; nj < 8; nj++){
                    int oc = oc0 + nj*8 + (lane & 3)*2;
                    if (oc < 200){
                        float v0 = (mk ? c[mi][nj][half*2+0] : 0.f) + __ldg(&bias[oc]);
                        float v1 = (mk ? c[mi][nj][half*2+1] : 0.f) + __ldg(&bias[oc+1]);
                        v0 = fmaxf(v0, 0.f); v1 = fmaxf(v1, 0.f);
                        __half2* orow = (__half2*)(Out + (size_t)n * 200 + oc);
                        *orow = __floats2half2_rn(v0, v1);
                    }
                }
            }
        }
    }
}

// ======================= merged HMMA GEMM (L2/L3/L4) =======================
static constexpr int STAGE = 32768;
static constexpr int SMEM_HM = 3 * STAGE + 512 + 3712;
static constexpr int SPLITC = 38;

// body after s_base/s_off setup; NT compile-time, oc_base runtime.
template <int NT, int OUTM>
DINLINE void hmma_body(const __half* __restrict__ B,
                       const float* __restrict__ bias, const int* __restrict__ mask,
                       void* __restrict__ Outv,
                       int oc_base, int Kpad, int NC, int OC, int P, int Nreal, int relu,
                       const __half* __restrict__ Src,
                       uint32_t sb, const int* s_base, const int* s_off,
                       int ICp, int Klayer)
{
    const int tid = threadIdx.x, lane = tid & 31, warp = tid >> 5;
    const int wm = warp >> 1, wn = warp & 1;

    const long ld = (long)Kpad;
    const int l_row = tid >> 3, l_ch = tid & 7;
    const uint32_t l_soff = (uint32_t)(l_row*128 + ((l_ch ^ (l_row&7))<<4));
    const __half* Bg = B + (size_t)(oc_base + l_row) * ld + l_ch*8;
    const long ld32 = 32*ld;

    const int cbase = (OUTM == 3) ? (int)blockIdx.z * SPLITC : 0;
    const int NCl   = (OUTM == 3) ? min(SPLITC, NC - cbase) : NC;

    auto loadA = [&](int chunk, uint32_t sA){
        int j = chunk*8 + l_ch;
        int k = j << 3;
        uint32_t sz = (k < Klayer) ? 16u : 0u;
        long off = sz ? (long)s_off[j] : 0;
#pragma unroll
        for (int i=0;i<4;i++){
            int row = l_row + i*32;
            const __half* src = Src + (size_t)s_base[row]*ICp + off;
            cp16z(sA + l_soff + i*4096, src, sz);
        }
    };
    auto loadB = [&](int chunk, uint32_t sB){
#pragma unroll
        for (int i=0;i<NT/32;i++) cp16(sB + l_soff + i*4096, Bg + chunk*64 + i*ld32);
    };

    const uint32_t rowA = (uint32_t)((wm*32 + (lane & 15)) * 128);
    const uint32_t rowB = (uint32_t)((wn*(NT/2) + (lane & 15)) * 128);
    const uint32_t chbase = (uint32_t)(lane >> 4);
    const uint32_t chxor  = (uint32_t)(lane & 7);

    constexpr int NJ = NT/16;
    constexpr int NB = (NT >= 64) ? NT/32 : 1;
    float c[2][NJ][4];
#pragma unroll
    for (int i=0;i<2;i++)
#pragma unroll
        for (int j=0;j<NJ;j++)
#pragma unroll
            for (int k=0;k<4;k++) c[i][j][k] = 0.f;

    loadA(cbase, sb);       loadB(cbase, sb + 16384);       cp_commit();
    if (NCl > 1){ loadA(cbase+1, sb + STAGE); loadB(cbase+1, sb + STAGE + 16384); }
    cp_commit();

#pragma unroll 1
    for (int cc = 0; cc < NCl; cc++){
        cp_wait1();
        __syncthreads();
        if (cc + 2 < NCl){
            uint32_t sA = sb + ((cc+2) % 3)*STAGE;
            loadA(cbase+cc+2, sA); loadB(cbase+cc+2, sA + 16384);
        }
        cp_commit();

        const uint32_t sA = sb + (cc % 3)*STAGE;
        const uint32_t sB = sA + 16384;
        const uint32_t aA0 = sA + rowA, aA1 = aA0 + 16*128;
        uint32_t aB[NB];
#pragma unroll
        for (int i=0;i<NB;i++) aB[i] = sB + rowB + i*16*128;

        uint32_t a[2][2][4], b[2][NB][4];
        {
            const uint32_t ch = (chbase ^ chxor) << 4;
            ldmx4(a[0][0], aA0 + ch); ldmx4(a[0][1], aA1 + ch);
#pragma unroll
            for (int i=0;i<NB;i++) ldmx4(b[0][i], aB[i] + ch);
        }
#pragma unroll
        for (int ks = 0; ks < 4; ks++){
            const int cur = ks & 1, nxt = cur ^ 1;
            if (ks < 3){
                const uint32_t ch = (((ks+1)*2 + chbase) ^ chxor) << 4;
                ldmx4(a[nxt][0], aA0 + ch); ldmx4(a[nxt][1], aA1 + ch);
#pragma unroll
                for (int i=0;i<NB;i++) ldmx4(b[nxt][i], aB[i] + ch);
            }
#pragma unroll
            for (int mi = 0; mi < 2; mi++)
#pragma unroll
                for (int nj = 0; nj < NJ; nj++)
                    mma_fp16(c[mi][nj], a[cur][mi],
                             b[cur][(NJ>2)?(nj>>1):0][nj&1],
                             b[cur][(NJ>2)?(nj>>1):0][2+(nj&1)]);
        }
    }

    const int gm0 = blockIdx.y*128 + wm*32;
    const int oc0 = oc_base + wn*(NT/2);
#pragma unroll
    for (int mi = 0; mi < 2; mi++){
#pragma unroll
        for (int half = 0; half < 2; half++){
            int n = gm0 + mi*16 + half*8 + (lane >> 2);
            if (n >= Nreal) continue;
            int mk = 1;
            if (OUTM != 3 && mask){ int p = n % P; mk = mask[p]; }
#pragma unroll
            for (int nj = 0; nj < NJ; nj++){
                int oc = oc0 + nj*8 + (lane & 3)*2;
                if (OUTM == 3){
                    int pcol = oc - oc_base;             // 0..31
                    float* o = (float*)Outv + (size_t)blockIdx.z*10880*32
                             + (size_t)n*32 + pcol;
                    float2 v = {c[mi][nj][half*2+0], c[mi][nj][half*2+1]};
                    *(float2*)o = v;
                } else if (oc < OC){
                    float v0 = (mk ? c[mi][nj][half*2+0] : 0.f) + __ldg(&bias[oc]);
                    float v1 = (mk ? c[mi][nj][half*2+1] : 0.f) + __ldg(&bias[oc+1]);
                    if (relu){ v0 = fmaxf(v0, 0.f); v1 = fmaxf(v1, 0.f); }
                    __half2* orow = (__half2*)((__half*)Outv + (size_t)n * OC + oc);
                    *orow = __floats2half2_rn(v0, v1);
                }
            }
        }
    }
}

template <int OUTM>
__global__ __launch_bounds__(256, 2)
void k_hmma(const __half* __restrict__ B,
            const float* __restrict__ bias, const int* __restrict__ mask,
            void* __restrict__ Outv,
            int gx128, int oc32_base, int Kpad, int NC, int OC, int P, int Nreal, int relu,
            const __half* __restrict__ Src, const int* __restrict__ selh,
            const int* __restrict__ selw, int IW, int ICp, int OW,
            int stride, int Klayer)
{
    extern __shared__ char smem[];
    const uint32_t sb = smem_u32(smem);
    int* s_base = (int*)(smem + 3*STAGE);
    int* s_off  = (int*)(smem + 3*STAGE + 512);
    const int tid = threadIdx.x;

    if (tid < 128){
        int n = blockIdx.y*128 + tid;
        if (n >= Nreal) n = Nreal - 1;
        int b = n / P, p = n - b*P;
        int oy = p / OW, ox = p - oy*OW;
        int ph = oy*stride + (selh ? selh[p] : 0);
        int pw = ox*stride + (selw ? selw[p] : 0);
        s_base[tid] = (b*IW + ph)*IW + pw;
    }
    for (int j = tid; j < (Klayer >> 3); j += 256){
        int k = j << 3;
        int tap = k / ICp, c = k - tap*ICp;
        int ky = tap/3, kx = tap - 3*ky;
        s_off[j] = (ky*IW + kx)*ICp + c;
    }
    __syncthreads();

    if ((int)blockIdx.x < gx128){
        hmma_body<128, OUTM>(B, bias, mask, Outv, blockIdx.x*128,
                             Kpad, NC, OC, P, Nreal, relu, Src,
                             sb, s_base, s_off, ICp, Klayer);
    } else {
        hmma_body<32, OUTM>(B, bias, mask, Outv,
                            oc32_base + ((int)blockIdx.x - gx128)*32,
                            Kpad, NC, OC, P, Nreal, relu, Src,
                            sb, s_base, s_off, ICp, Klayer);
    }
}

// ======================= launch =======================
extern "C" void kernel_launch(void* const* d_in, const int* in_sizes, int n_in,
                              void* d_out, int out_size) {
    const float* x     = (const float*)d_in[0];
    const float* w1    = (const float*)d_in[1];
    const float* b1    = (const float*)d_in[2];
    const float* w2    = (const float*)d_in[3];
    const float* b2    = (const float*)d_in[4];
    const float* w3    = (const float*)d_in[5];
    const float* b3    = (const float*)d_in[6];
    const float* w4    = (const float*)d_in[7];
    const float* b4    = (const float*)d_in[8];
    const int*   selh1 = (const int*)d_in[9];
    const int*   selw1 = (const int*)d_in[10];
    const int*   mask1 = (const int*)d_in[11];
    const int*   selh2 = (const int*)d_in[12];
    const int*   selw2 = (const int*)d_in[13];
    const int*   mask2 = (const int*)d_in[14];
    const int*   selh3 = (const int*)d_in[15];
    const int*   selw3 = (const int*)d_in[16];
    const int*   mask3 = (const int*)d_in[17];

    float *pP4;
    __half *pO1, *pO2, *pO3, *pA1, *pB1, *pB2, *pB3, *pB4;
    cudaGetSymbolAddress((void**)&pO1, g_O1);
    cudaGetSymbolAddress((void**)&pO2, g_O2);
    cudaGetSymbolAddress((void**)&pO3, g_O3);
    cudaGetSymbolAddress((void**)&pP4, g_P4);
    cudaGetSymbolAddress((void**)&pA1, g_A1);
    cudaGetSymbolAddress((void**)&pB1, g_B1);
    cudaGetSymbolAddress((void**)&pB2, g_B2);
    cudaGetSymbolAddress((void**)&pB3, g_B3);
    cudaGetSymbolAddress((void**)&pB4, g_B4);

    cudaFuncSetAttribute((const void*)k_hmma1,
                         cudaFuncAttributeMaxDynamicSharedMemorySize, SMEM_L1);
    cudaFuncSetAttribute((const void*)k_hmma<1>,
                         cudaFuncAttributeMaxDynamicSharedMemorySize, SMEM_HM);
    cudaFuncSetAttribute((const void*)k_hmma<3>,
                         cudaFuncAttributeMaxDynamicSharedMemorySize, SMEM_HM);

    // ---- weight conversions (one launch) + L1 gather ----
    k_wcvt_all<<<(unsigned)((WC4 + 255) / 256), 256>>>(w1, w2, w3, w4,
                                                       pB1, pB2, pB3, pB4);
    k_gather1<<<(270592 + 255) / 256, 256>>>(x, pA1, selh1, selw1);

    // ---- layer 1: persistent-B GEMM, K=32 ----
    k_hmma1<<<dim3(2, 148), 256, SMEM_L1>>>(pA1, pB1, b1, mask1, pO1);

    // ---- layer 2: merged main(3x128) + tail(1x32), grid (4,482) ----
    k_hmma<1><<<dim3(4, 482), 256, SMEM_HM>>>(
        pB2, b2, mask2, pO2, 3, 384, 1856, 29, 400, 961, 61504, 1,
        pO1, selh2, selw2, 65, 200, 31, 2, 1800);

    // ---- layer 3: merged main(6x128) + tail(1x32), grid (7,114) ----
    k_hmma<1><<<dim3(7, 114), 256, SMEM_HM>>>(
        pB3, b3, mask3, pO3, 6, 768, 3648, 57, 800, 225, 14400, 1,
        pO2, selh3, selw3, 31, 400, 15, 2, 3600);

    // ---- layer 4: NT=32 dense GEMM, split-K x3 partials + combine ----
    k_hmma<3><<<dim3(1, 85, 3), 256, SMEM_HM>>>(
        pB4, b4, nullptr, pP4, 0, 0, 7232, 113, 10, 169, 10816, 0,
        pO3, nullptr, nullptr, 15, 800, 13, 1, 7200);
    k_out4<<<(108160 + 255) / 256, 256>>>(pP4, b4, (float*)d_out);
}